// round 2
// baseline (speedup 1.0000x reference)
#include <cuda_runtime.h>

#define CL 8192
#define CD 512
#define CB 4

// ---------------- scratch (device globals; no allocation) ----------------
__device__ float g_qc[CB*CD*CL];      // q, channel-major (B, D, L)
__device__ float g_o1[16*128*CL];     // conv1 out, channel-major (BG, GC, L)
__device__ float g_offs[16*CL];       // offsets (BG, L)
__device__ float g_xs[CB*CL*CD];      // sampled x, row-major (B*L, D)
__device__ float g_kc[CB*CD*CL];      // k, channel-major
__device__ float g_vt[CB*CL*CD];      // v, row-major (B*L, D)
__device__ float g_rbt[CL*CD];        // rel_bias transposed (L, D)
__device__ float g_part[8*32*64*64];  // score partials (chunk, BH, 64, 64)
__device__ float g_attn[32*64*64];
__device__ float g_weff[CB*CD*CD];    // folded attn+Wout per batch

// ---------------- rel_bias transpose: (D,L) -> (L,D) ----------------
__global__ void transpose_rb(const float* __restrict__ rb)
{
    __shared__ float t[32][33];
    int l0 = blockIdx.x * 32, d0 = blockIdx.y * 32;
    int tx = threadIdx.x, ty = threadIdx.y;  // (32, 8)
    #pragma unroll
    for (int r = 0; r < 32; r += 8)
        t[ty + r][tx] = rb[(size_t)(d0 + ty + r) * CL + l0 + tx];
    __syncthreads();
    #pragma unroll
    for (int r = 0; r < 32; r += 8)
        g_rbt[(size_t)(l0 + ty + r) * CD + d0 + tx] = t[tx][ty + r];
}

// ---------------- GEMM, channel-major output ----------------
// out[(b*512 + m)*L + n] = sum_k W[m*512+k] * X[(b*L+n)*512 + k] + bias[m]
// mode 0: X = Xp (input x), out = g_qc.  mode 1: X = g_xs, out = g_kc.
__global__ __launch_bounds__(256, 2)
void gemm_cm(const float* __restrict__ Xp, const float* __restrict__ W,
             const float* __restrict__ bias, int mode)
{
    __shared__ __align__(16) float As[16][132];  // [k][m]
    __shared__ __align__(16) float Bs[16][132];  // [k][n]
    const float* X  = mode ? g_xs : Xp;
    float* out      = mode ? g_kc : g_qc;
    int tid = threadIdx.x;
    int tx = tid & 15, ty = tid >> 4;
    int m0 = blockIdx.y * 128, n0 = blockIdx.x * 128;
    int b  = blockIdx.z;
    const float* Xb = X + (size_t)b * CL * CD;
    float acc[8][8] = {};
    for (int k0 = 0; k0 < CD; k0 += 16) {
        #pragma unroll
        for (int it = 0; it < 2; it++) {
            int id = tid + it * 256;
            int row = id >> 2, kq = (id & 3) << 2;
            float4 v = *(const float4*)(W + (size_t)(m0 + row) * CD + k0 + kq);
            As[kq+0][row] = v.x; As[kq+1][row] = v.y; As[kq+2][row] = v.z; As[kq+3][row] = v.w;
            float4 u = *(const float4*)(Xb + (size_t)(n0 + row) * CD + k0 + kq);
            Bs[kq+0][row] = u.x; Bs[kq+1][row] = u.y; Bs[kq+2][row] = u.z; Bs[kq+3][row] = u.w;
        }
        __syncthreads();
        #pragma unroll
        for (int k = 0; k < 16; k++) {
            float a[8], bb[8];
            *(float4*)&a[0]  = *(const float4*)&As[k][ty*8];
            *(float4*)&a[4]  = *(const float4*)&As[k][ty*8+4];
            *(float4*)&bb[0] = *(const float4*)&Bs[k][tx*8];
            *(float4*)&bb[4] = *(const float4*)&Bs[k][tx*8+4];
            #pragma unroll
            for (int i = 0; i < 8; i++)
                #pragma unroll
                for (int j = 0; j < 8; j++)
                    acc[i][j] += a[i] * bb[j];
        }
        __syncthreads();
    }
    #pragma unroll
    for (int i = 0; i < 8; i++) {
        int m = m0 + ty*8 + i;
        float bi = bias[m];
        float* o = out + ((size_t)b * CD + m) * CL + n0 + tx*8;
        #pragma unroll
        for (int j = 0; j < 8; j++) o[j] = acc[i][j] + bi;
    }
}

// ---------------- GEMM, row-major output ----------------
// mode 0 (v):    A = g_xs, W = Wp (Wv), out = g_vt, add rel_bias from g_rbt
// mode 1 (final):A = g_vt, W = g_weff (per-batch), out = outp
__global__ __launch_bounds__(256, 2)
void gemm_rm(const float* __restrict__ Wp, const float* __restrict__ bias,
             float* __restrict__ outp, int mode)
{
    __shared__ __align__(16) float As[16][132];
    __shared__ __align__(16) float Bs[16][132];
    int tid = threadIdx.x;
    int tx = tid & 15, ty = tid >> 4;
    int n0 = blockIdx.x * 128;
    size_t m0 = (size_t)blockIdx.y * 128;
    const float* A = mode ? g_vt : g_xs;
    const float* W = mode ? (g_weff + (m0 >> 13) * (size_t)CD * CD) : Wp;
    float* out     = mode ? outp : g_vt;
    float acc[8][8] = {};
    for (int k0 = 0; k0 < CD; k0 += 16) {
        #pragma unroll
        for (int it = 0; it < 2; it++) {
            int id = tid + it * 256;
            int row = id >> 2, kq = (id & 3) << 2;
            float4 v = *(const float4*)(A + (m0 + row) * CD + k0 + kq);
            As[kq+0][row] = v.x; As[kq+1][row] = v.y; As[kq+2][row] = v.z; As[kq+3][row] = v.w;
            float4 u = *(const float4*)(W + (size_t)(n0 + row) * CD + k0 + kq);
            Bs[kq+0][row] = u.x; Bs[kq+1][row] = u.y; Bs[kq+2][row] = u.z; Bs[kq+3][row] = u.w;
        }
        __syncthreads();
        #pragma unroll
        for (int k = 0; k < 16; k++) {
            float a[8], bb[8];
            *(float4*)&a[0]  = *(const float4*)&As[k][ty*8];
            *(float4*)&a[4]  = *(const float4*)&As[k][ty*8+4];
            *(float4*)&bb[0] = *(const float4*)&Bs[k][tx*8];
            *(float4*)&bb[4] = *(const float4*)&Bs[k][tx*8+4];
            #pragma unroll
            for (int i = 0; i < 8; i++)
                #pragma unroll
                for (int j = 0; j < 8; j++)
                    acc[i][j] += a[i] * bb[j];
        }
        __syncthreads();
    }
    #pragma unroll
    for (int i = 0; i < 8; i++) {
        size_t m = m0 + ty*8 + i;
        float* o = out + m * CD + n0 + tx*8;
        const float* rbrow = g_rbt + (size_t)(m & (CL-1)) * CD + n0 + tx*8;
        #pragma unroll
        for (int j = 0; j < 8; j++) {
            float v = acc[i][j] + bias[n0 + tx*8 + j];
            if (!mode) v += rbrow[j];
            o[j] = v;
        }
    }
}

// ---------------- conv1: o1[bg][co][l] = sum_{ci,t} W1[co][ci][t]*qc[bg][ci][l+t-2] + b1[co]
__global__ __launch_bounds__(256, 2)
void conv1_k(const float* __restrict__ W1, const float* __restrict__ b1)
{
    __shared__ float Ws[128 * 40];   // [co][ci(8)][t(5)]
    __shared__ float In[8 * 132];    // [ci][l0-2 .. l0+129]
    int tid = threadIdx.x, tx = tid & 15, ty = tid >> 4;
    int bg = blockIdx.y;
    int l0 = blockIdx.x * 128;
    const float* src = g_qc + (size_t)bg * 128 * CL;
    float acc[8][8] = {};
    for (int c0 = 0; c0 < 128; c0 += 8) {
        for (int idx = tid; idx < 128 * 40; idx += 256) {
            int co = idx / 40, r = idx - co * 40;
            int ci = r / 5, t = r - ci * 5;
            Ws[idx] = W1[co * 640 + (c0 + ci) * 5 + t];
        }
        for (int idx = tid; idx < 8 * 132; idx += 256) {
            int ci = idx / 132, j = idx - ci * 132;
            int l = l0 - 2 + j;
            In[idx] = (l >= 0 && l < CL) ? src[(size_t)(c0 + ci) * CL + l] : 0.f;
        }
        __syncthreads();
        #pragma unroll
        for (int ci = 0; ci < 8; ci++) {
            float xv[12];
            #pragma unroll
            for (int j = 0; j < 12; j++) xv[j] = In[ci * 132 + tx*8 + j];
            #pragma unroll
            for (int t = 0; t < 5; t++) {
                float w[8];
                #pragma unroll
                for (int i = 0; i < 8; i++) w[i] = Ws[(ty*8 + i) * 40 + ci * 5 + t];
                #pragma unroll
                for (int i = 0; i < 8; i++)
                    #pragma unroll
                    for (int j = 0; j < 8; j++)
                        acc[i][j] += w[i] * xv[j + t];
            }
        }
        __syncthreads();
    }
    #pragma unroll
    for (int i = 0; i < 8; i++) {
        int co = ty*8 + i;
        float bb = b1[co];
        float* dst = g_o1 + ((size_t)bg * 128 + co) * CL + l0 + tx*8;
        #pragma unroll
        for (int j = 0; j < 8; j++) dst[j] = acc[i][j] + bb;
    }
}

// ---------------- offsets: offs[bg][lq] = 5*tanh(b2 + sum_ci w2[ci]*o1pad[ci][lq-2])
__global__ void offsets_k(const float* __restrict__ w2, const float* __restrict__ b2)
{
    __shared__ float tile[64 * 128];
    __shared__ float w2s[128];
    int tid = threadIdx.x;  // 128
    int bg = blockIdx.y;
    int lq0 = blockIdx.x * 128;
    w2s[tid] = w2[tid];
    float sum = 0.f;
    for (int half = 0; half < 2; half++) {
        __syncthreads();
        for (int idx = tid; idx < 64 * 128; idx += 128) {
            int ci = idx >> 7, li = idx & 127;
            int l = lq0 - 2 + li;             // top side always < L
            tile[idx] = (l >= 0) ? g_o1[((size_t)bg * 128 + half * 64 + ci) * CL + l] : 0.f;
        }
        __syncthreads();
        for (int ci = 0; ci < 64; ci++) sum += w2s[half * 64 + ci] * tile[ci * 128 + tid];
    }
    g_offs[(size_t)bg * CL + lq0 + tid] = 5.f * tanhf(sum + b2[0]);
}

// ---------------- bilinear sampler -> xs row-major (B*L, D)
__global__ void sampler_k(const float* __restrict__ x)
{
    int blk = blockIdx.x;                  // b*8192 + l
    int b = blk >> 13, l = blk & (CL - 1);
    int tid = threadIdx.x;                 // 128
    int d4 = tid * 4;
    int g = tid >> 5;
    float off = g_offs[(size_t)(b * 4 + g) * CL + l];
    float vg = (float)l + off;
    float gg = 2.f * vg / 8195.f - 1.f;
    float ps = ((gg + 1.f) * 8192.f - 1.f) * 0.5f;
    float p0 = floorf(ps);
    float w1 = ps - p0;
    int i0 = (int)p0, i1 = i0 + 1;
    float4 a = make_float4(0.f, 0.f, 0.f, 0.f);
    float4 c = make_float4(0.f, 0.f, 0.f, 0.f);
    if (i0 >= 0 && i0 < CL) a = *(const float4*)(x + ((size_t)b * CL + i0) * CD + d4);
    if (i1 >= 0 && i1 < CL) c = *(const float4*)(x + ((size_t)b * CL + i1) * CD + d4);
    float w0 = 1.f - w1;
    float4 r;
    r.x = a.x * w0 + c.x * w1;
    r.y = a.y * w0 + c.y * w1;
    r.z = a.z * w0 + c.z * w1;
    r.w = a.w * w0 + c.w * w1;
    *(float4*)(g_xs + ((size_t)b * CL + l) * CD + d4) = r;
}

// ---------------- scores: split-K over L into 8 deterministic partials
__global__ __launch_bounds__(256, 2)
void scores_k()
{
    __shared__ __align__(16) float Qs[32][68];
    __shared__ __align__(16) float Ks[32][68];
    int tid = threadIdx.x, tx = tid & 15, ty = tid >> 4;
    int bh = blockIdx.x;                     // b*8 + h
    int chunk = blockIdx.y;                  // 8 chunks of 1024
    size_t base = (size_t)bh * 64 * CL;      // (b*512 + h*64)*L
    int l0 = chunk * 1024;
    float acc[4][4] = {};
    for (int lc = 0; lc < 1024; lc += 32) {
        int lb = l0 + lc;
        for (int idx = tid; idx < 2048; idx += 256) {
            int i = idx >> 5, lk = idx & 31;
            Qs[lk][i] = g_qc[base + (size_t)i * CL + lb + lk];
            Ks[lk][i] = g_kc[base + (size_t)i * CL + lb + lk];
        }
        __syncthreads();
        #pragma unroll
        for (int lk = 0; lk < 32; lk++) {
            float qv[4], kv[4];
            *(float4*)qv = *(const float4*)&Qs[lk][ty*4];
            *(float4*)kv = *(const float4*)&Ks[lk][tx*4];
            #pragma unroll
            for (int i = 0; i < 4; i++)
                #pragma unroll
                for (int j = 0; j < 4; j++)
                    acc[i][j] += qv[i] * kv[j];
        }
        __syncthreads();
    }
    float* dst = g_part + ((size_t)chunk * 32 + bh) * 4096;
    #pragma unroll
    for (int i = 0; i < 4; i++)
        #pragma unroll
        for (int j = 0; j < 4; j++)
            dst[(ty*4 + i) * 64 + tx*4 + j] = acc[i][j];
}

// ---------------- reduce partials + scale + softmax over j ----------------
__global__ void softmax_k()
{
    int bh = blockIdx.x, i = threadIdx.x;   // 64 threads = rows
    const float scale = 0.04419417382415922f;  // 512^-0.5
    float v[64];
    for (int j = 0; j < 64; j++) {
        float s = 0.f;
        #pragma unroll
        for (int c = 0; c < 8; c++) s += g_part[((size_t)c * 32 + bh) * 4096 + i * 64 + j];
        v[j] = s * scale;
    }
    float mx = v[0];
    for (int j = 1; j < 64; j++) mx = fmaxf(mx, v[j]);
    float sum = 0.f;
    for (int j = 0; j < 64; j++) { v[j] = expf(v[j] - mx); sum += v[j]; }
    float inv = 1.f / sum;
    for (int j = 0; j < 64; j++) g_attn[(size_t)bh * 4096 + i * 64 + j] = v[j] * inv;
}

// ---------------- W_eff[b][o][h*64+j] = sum_i Wout[o][h*64+i]*attn[b][h][i][j]
__global__ void weff_k(const float* __restrict__ Wout)
{
    __shared__ float As[64 * 64];
    int b = blockIdx.x, h = blockIdx.y, tid = threadIdx.x;  // 256 threads
    for (int idx = tid; idx < 4096; idx += 256)
        As[idx] = g_attn[((size_t)(b * 8 + h)) * 4096 + idx];
    __syncthreads();
    for (int o = tid; o < CD; o += 256) {
        float wr[64];
        #pragma unroll
        for (int i = 0; i < 64; i++) wr[i] = Wout[(size_t)o * CD + h * 64 + i];
        for (int j = 0; j < 64; j++) {
            float s = 0.f;
            #pragma unroll
            for (int i = 0; i < 64; i++) s += wr[i] * As[i * 64 + j];
            g_weff[((size_t)b * CD + o) * CD + h * 64 + j] = s;
        }
    }
}

// ---------------- launch ----------------
extern "C" void kernel_launch(void* const* d_in, const int* in_sizes, int n_in,
                              void* d_out, int out_size)
{
    const float* x     = (const float*)d_in[0];
    const float* Wq    = (const float*)d_in[1];
    const float* bq    = (const float*)d_in[2];
    const float* Wk    = (const float*)d_in[3];
    const float* bk    = (const float*)d_in[4];
    const float* Wv    = (const float*)d_in[5];
    const float* bv    = (const float*)d_in[6];
    const float* Woff1 = (const float*)d_in[7];
    const float* boff1 = (const float*)d_in[8];
    const float* Woff2 = (const float*)d_in[9];
    const float* boff2 = (const float*)d_in[10];
    const float* relb  = (const float*)d_in[11];
    const float* Wout  = (const float*)d_in[12];
    const float* bout  = (const float*)d_in[13];
    float* out = (float*)d_out;

    transpose_rb<<<dim3(CL/32, CD/32), dim3(32, 8)>>>(relb);
    gemm_cm<<<dim3(64, 4, CB), 256>>>(x, Wq, bq, 0);         // q (chan-major)
    conv1_k<<<dim3(64, 16), 256>>>(Woff1, boff1);            // offset conv1
    offsets_k<<<dim3(64, 16), 128>>>(Woff2, boff2);          // conv2 + tanh
    sampler_k<<<CB*CL, 128>>>(x);                            // bilinear gather
    gemm_cm<<<dim3(64, 4, CB), 256>>>(nullptr, Wk, bk, 1);   // k (chan-major)
    gemm_rm<<<dim3(4, 256), 256>>>(Wv, bv, nullptr, 0);      // v (+rel_bias)
    scores_k<<<dim3(32, 8), 256>>>();                        // q·kᵀ split-K
    softmax_k<<<32, 64>>>();                                 // reduce+softmax
    weff_k<<<dim3(CB, 8), 256>>>(Wout);                      // fold attn into Wout
    gemm_rm<<<dim3(4, 256), 256>>>(nullptr, bout, out, 1);   // y = v·W_effᵀ
}

// round 4
// speedup vs baseline: 1.9528x; 1.9528x over previous
#include <cuda_runtime.h>
#include <cuda_bf16.h>
#include <cstdint>

#define CL 8192
#define CD 512
#define CB 4

// ---------------- scratch (device globals; no allocation) ----------------
__device__ float g_qc[CB*CD*CL];      // q, channel-major (B, D, L)
__device__ float g_o1[16*128*CL];     // conv1 out, channel-major (BG, GC, L)
__device__ float g_offs[16*CL];       // offsets (BG, L)
__device__ float g_xs[CB*CL*CD];      // sampled x, row-major (B*L, D)
__device__ float g_kc[CB*CD*CL];      // k, channel-major
__device__ float g_vt[CB*CL*CD];      // v, row-major (B*L, D)
__device__ float g_rbt[CL*CD];        // rel_bias transposed (L, D)
__device__ float g_part[8*32*64*64];  // score partials (chunk, BH, 64, 64)
__device__ float g_attn[32*64*64];
__device__ float g_weff[CB*CD*CD];    // folded attn+Wout per batch

// ======================= mma.sync helpers (portable, sm_80+) =======================
__device__ __forceinline__ uint32_t smem_u32(const void* p){
    uint32_t a;
    asm("{ .reg .u64 t; cvta.to.shared.u64 t, %1; cvt.u32.u64 %0, t; }" : "=r"(a) : "l"(p));
    return a;
}
__device__ __forceinline__ void mma_bf16(float* c, const uint32_t* a, const uint32_t* b){
    asm volatile("mma.sync.aligned.m16n8k16.row.col.f32.bf16.bf16.f32 "
        "{%0,%1,%2,%3}, {%4,%5,%6,%7}, {%8,%9}, {%0,%1,%2,%3};"
        : "+f"(c[0]), "+f"(c[1]), "+f"(c[2]), "+f"(c[3])
        : "r"(a[0]), "r"(a[1]), "r"(a[2]), "r"(a[3]), "r"(b[0]), "r"(b[1]));
}
__device__ __forceinline__ void ldsm4(uint32_t* r, uint32_t addr){
    asm volatile("ldmatrix.sync.aligned.m8n8.x4.shared.b16 {%0,%1,%2,%3}, [%4];"
        : "=r"(r[0]), "=r"(r[1]), "=r"(r[2]), "=r"(r[3]) : "r"(addr));
}
__device__ __forceinline__ void ldsm2(uint32_t* r, uint32_t addr){
    asm volatile("ldmatrix.sync.aligned.m8n8.x2.shared.b16 {%0,%1}, [%2];"
        : "=r"(r[0]), "=r"(r[1]) : "r"(addr));
}

// convert 16 fp32 -> bf16 hi plane + bf16 lo plane (residual), 8B stores
__device__ __forceinline__ void cvt_store16(char* hi, char* lo, const float* p){
    #pragma unroll
    for (int c = 0; c < 16; c += 4) {
        float4 v = *(const float4*)(p + c);
        __nv_bfloat162 h01, h23, l01, l23;
        h01.x = __float2bfloat16(v.x); h01.y = __float2bfloat16(v.y);
        h23.x = __float2bfloat16(v.z); h23.y = __float2bfloat16(v.w);
        *(uint2*)(hi + c*2) = make_uint2(*(uint32_t*)&h01, *(uint32_t*)&h23);
        l01.x = __float2bfloat16(v.x - __bfloat162float(h01.x));
        l01.y = __float2bfloat16(v.y - __bfloat162float(h01.y));
        l23.x = __float2bfloat16(v.z - __bfloat162float(h23.x));
        l23.y = __float2bfloat16(v.w - __bfloat162float(h23.y));
        *(uint2*)(lo + c*2) = make_uint2(*(uint32_t*)&l01, *(uint32_t*)&l23);
    }
}
__device__ __forceinline__ void cvt_store8(char* hi, char* lo, const float* p){
    #pragma unroll
    for (int c = 0; c < 8; c += 4) {
        float4 v = *(const float4*)(p + c);
        __nv_bfloat162 h01, h23, l01, l23;
        h01.x = __float2bfloat16(v.x); h01.y = __float2bfloat16(v.y);
        h23.x = __float2bfloat16(v.z); h23.y = __float2bfloat16(v.w);
        *(uint2*)(hi + c*2) = make_uint2(*(uint32_t*)&h01, *(uint32_t*)&h23);
        l01.x = __float2bfloat16(v.x - __bfloat162float(h01.x));
        l01.y = __float2bfloat16(v.y - __bfloat162float(h01.y));
        l23.x = __float2bfloat16(v.z - __bfloat162float(h23.x));
        l23.y = __float2bfloat16(v.w - __bfloat162float(h23.y));
        *(uint2*)(lo + c*2) = make_uint2(*(uint32_t*)&l01, *(uint32_t*)&l23);
    }
}

#define STRB 80                 // bytes per plane row (32 bf16 + pad) — conflict-free for ldmatrix
#define PL   10240              // plane bytes (128 rows * 80)
#define BUF  40960              // Ahi,Alo,Bhi,Blo
#define GSMEM (2*BUF)           // 81920

// consume one Kc=32 chunk: 3 split products x 2 ksteps, warp tile 64x32 (4x4 mma tiles)
__device__ __forceinline__ void mma_chunk128(float acc[4][4][4], uint32_t s0, int wm, int wn, int lane){
    #pragma unroll
    for (int p = 0; p < 3; p++) {
        uint32_t pA = s0 + ((p == 2) ? PL : 0);
        uint32_t pB = s0 + 2*PL + ((p == 1) ? PL : 0);
        #pragma unroll
        for (int ks = 0; ks < 2; ks++) {
            uint32_t af[4][4], bf[4][2];
            #pragma unroll
            for (int i = 0; i < 4; i++)
                ldsm4(af[i], pA + (wm*64 + i*16 + (lane & 15))*STRB + ks*32 + (lane >> 4)*16);
            #pragma unroll
            for (int j = 0; j < 4; j++)
                ldsm2(bf[j], pB + (wn*32 + j*8 + (lane & 7))*STRB + ks*32 + ((lane >> 3) & 1)*16);
            #pragma unroll
            for (int i = 0; i < 4; i++)
                #pragma unroll
                for (int j = 0; j < 4; j++)
                    mma_bf16(acc[i][j], af[i], bf[j]);
        }
    }
}

// ======================= unified big GEMM (mma.sync split-bf16) =======================
// C[128,128] = A·Bᵀ, K=512 fp32. modes:
// 0: q = Wq·x   -> g_qc chan-major (grid x=Ltile64, y=Dtile4, z=b)
// 1: k = Wk·xs  -> g_kc chan-major
// 2: v = xs·Wvᵀ -> g_vt row-major + bv + rel_bias (grid x=Dtile4, y=Ltile64, z=b)
// 3: out = vt·Weffᵀ -> Out row-major + bout
__global__ __launch_bounds__(256)
void gemm_mma(const float* __restrict__ W, const float* __restrict__ Xin,
              const float* __restrict__ bias, float* __restrict__ Out, int mode)
{
    extern __shared__ __align__(16) char smem[];
    uint32_t sb = smem_u32(smem);
    int tid = threadIdx.x, lane = tid & 31, wid = tid >> 5;
    int wm = wid >> 2, wn = wid & 3;
    int bx = blockIdx.x, by = blockIdx.y, bz = blockIdx.z;

    const float *A, *Bm;
    if (mode == 0)      { A = W + (size_t)by*128*CD;              Bm = Xin  + ((size_t)bz*CL + bx*128)*CD; }
    else if (mode == 1) { A = W + (size_t)by*128*CD;              Bm = g_xs + ((size_t)bz*CL + bx*128)*CD; }
    else if (mode == 2) { A = g_xs + ((size_t)bz*CL + by*128)*CD; Bm = W + (size_t)bx*128*CD; }
    else                { A = g_vt + ((size_t)bz*CL + by*128)*CD; Bm = g_weff + (size_t)bz*CD*CD + (size_t)bx*128*CD; }

    int r = tid >> 1, c0 = (tid & 1) * 16;
    const float* pa = A  + (size_t)r*CD + c0;
    const float* pb = Bm + (size_t)r*CD + c0;

    float acc[4][4][4] = {};

    // fill chunk 0
    {
        char* s = smem;
        cvt_store16(s +        r*STRB + c0*2, s + PL   + r*STRB + c0*2, pa);
        cvt_store16(s + 2*PL + r*STRB + c0*2, s + 3*PL + r*STRB + c0*2, pb);
    }
    for (int ch = 0; ch < 16; ch++) {
        __syncthreads();
        if (ch + 1 < 16) {
            char* s = smem + ((ch+1) & 1)*BUF;
            int k = (ch+1)*32;
            cvt_store16(s +        r*STRB + c0*2, s + PL   + r*STRB + c0*2, pa + k);
            cvt_store16(s + 2*PL + r*STRB + c0*2, s + 3*PL + r*STRB + c0*2, pb + k);
        }
        mma_chunk128(acc, sb + (ch & 1)*BUF, wm, wn, lane);
    }

    int qr = lane >> 2, qc = (lane & 3)*2;
    if (mode <= 1) {
        float* C = mode ? g_kc : g_qc;
        #pragma unroll
        for (int i = 0; i < 4; i++) {
            #pragma unroll
            for (int half = 0; half < 2; half++) {
                int m = by*128 + wm*64 + i*16 + qr + half*8;
                float bm = bias[m];
                float* dst = C + ((size_t)bz*CD + m)*CL + bx*128 + wn*32 + qc;
                #pragma unroll
                for (int j = 0; j < 4; j++) {
                    float2 v;
                    v.x = acc[i][j][half*2+0] + bm;
                    v.y = acc[i][j][half*2+1] + bm;
                    *(float2*)(dst + j*8) = v;
                }
            }
        }
    } else {
        #pragma unroll
        for (int i = 0; i < 4; i++) {
            #pragma unroll
            for (int half = 0; half < 2; half++) {
                int lrow = by*128 + wm*64 + i*16 + qr + half*8;    // absolute l
                float* dst = (mode == 2 ? g_vt : Out) + ((size_t)bz*CL + lrow)*CD + bx*128 + wn*32 + qc;
                const float* bn = bias + bx*128 + wn*32 + qc;
                const float* rp = g_rbt + (size_t)lrow*CD + bx*128 + wn*32 + qc;
                #pragma unroll
                for (int j = 0; j < 4; j++) {
                    float2 v;
                    v.x = acc[i][j][half*2+0] + bn[j*8+0];
                    v.y = acc[i][j][half*2+1] + bn[j*8+1];
                    if (mode == 2) { v.x += rp[j*8+0]; v.y += rp[j*8+1]; }
                    *(float2*)(dst + j*8) = v;
                }
            }
        }
    }
}

// ======================= conv1 as im2col GEMM (K=640) =======================
// o1[bg][co][l] = sum_{ci,t} W1[co][ci*5+t] * qc[bg][ci][l0+l+t-2] + b1[co]
__global__ __launch_bounds__(256)
void conv_mma(const float* __restrict__ W1, const float* __restrict__ b1)
{
    extern __shared__ __align__(16) char smem[];
    uint32_t sb = smem_u32(smem);
    int tid = threadIdx.x, lane = tid & 31, wid = tid >> 5;
    int wm = wid >> 2, wn = wid & 3;
    int l0 = blockIdx.x * 128, bg = blockIdx.y;
    const float* src = g_qc + (size_t)bg * 128 * CL;

    int r = tid >> 1, c0 = (tid & 1) * 16;
    const float* pa = W1 + (size_t)r*640 + c0;

    float acc[4][4][4] = {};

    auto fill = [&](int buf, int ch){
        char* s = smem + buf*BUF;
        cvt_store16(s + r*STRB + c0*2, s + PL + r*STRB + c0*2, pa + ch*32);
        char* bh = s + 2*PL + r*STRB + c0*2;
        char* bl = s + 3*PL + r*STRB + c0*2;
        #pragma unroll
        for (int c = 0; c < 16; c++) {
            int k = ch*32 + c0 + c;
            int ci = (k * 205) >> 10;       // exact k/5 for k < 640
            int t  = k - ci*5;
            int l  = l0 + r + t - 2;
            float v = (l >= 0 && l < CL) ? src[(size_t)ci*CL + l] : 0.f;
            __nv_bfloat16 h = __float2bfloat16(v);
            __nv_bfloat16 lo = __float2bfloat16(v - __bfloat162float(h));
            *(__nv_bfloat16*)(bh + c*2) = h;
            *(__nv_bfloat16*)(bl + c*2) = lo;
        }
    };

    fill(0, 0);
    for (int ch = 0; ch < 20; ch++) {
        __syncthreads();
        if (ch + 1 < 20) fill((ch+1) & 1, ch+1);
        mma_chunk128(acc, sb + (ch & 1)*BUF, wm, wn, lane);
    }

    int qr = lane >> 2, qc = (lane & 3)*2;
    #pragma unroll
    for (int i = 0; i < 4; i++) {
        #pragma unroll
        for (int half = 0; half < 2; half++) {
            int co = wm*64 + i*16 + qr + half*8;
            float bm = b1[co];
            float* dst = g_o1 + ((size_t)(bg*128 + co))*CL + l0 + wn*32 + qc;
            #pragma unroll
            for (int j = 0; j < 4; j++) {
                float2 v;
                v.x = acc[i][j][half*2+0] + bm;
                v.y = acc[i][j][half*2+1] + bm;
                *(float2*)(dst + j*8) = v;
            }
        }
    }
}

// ======================= scores: C[64,64] = q·kᵀ over K=1024 L-chunk =======================
#define PS   5120               // 64 rows * 80
#define BUFS 20480
__global__ __launch_bounds__(256)
void scores_mma()
{
    extern __shared__ __align__(16) char smem[];
    uint32_t sb = smem_u32(smem);
    int tid = threadIdx.x, lane = tid & 31, wid = tid >> 5;
    int wm = wid >> 2, wn = wid & 3;      // wm: 2x32 rows, wn: 4x16 cols
    int bh = blockIdx.x, chunk = blockIdx.y;
    size_t chbase = (size_t)(bh >> 3)*CD + (size_t)(bh & 7)*64;
    const float* qb = g_qc + chbase*CL + (size_t)chunk*1024;
    const float* kb = g_kc + chbase*CL + (size_t)chunk*1024;

    int r = tid >> 2, c0 = (tid & 3)*8;   // 64 rows, 4 threads/row

    float acc[2][2][4] = {};

    auto fill = [&](int buf, int ch){
        char* s = smem + buf*BUFS;
        cvt_store8(s +        r*STRB + c0*2, s + PS   + r*STRB + c0*2, qb + (size_t)r*CL + ch*32 + c0);
        cvt_store8(s + 2*PS + r*STRB + c0*2, s + 3*PS + r*STRB + c0*2, kb + (size_t)r*CL + ch*32 + c0);
    };

    fill(0, 0);
    for (int ch = 0; ch < 32; ch++) {
        __syncthreads();
        if (ch + 1 < 32) fill((ch+1) & 1, ch+1);
        uint32_t s0 = sb + (ch & 1)*BUFS;
        #pragma unroll
        for (int p = 0; p < 3; p++) {
            uint32_t pA = s0 + ((p == 2) ? PS : 0);
            uint32_t pB = s0 + 2*PS + ((p == 1) ? PS : 0);
            #pragma unroll
            for (int ks = 0; ks < 2; ks++) {
                uint32_t af[2][4], bf[2][2];
                #pragma unroll
                for (int i = 0; i < 2; i++)
                    ldsm4(af[i], pA + (wm*32 + i*16 + (lane & 15))*STRB + ks*32 + (lane >> 4)*16);
                #pragma unroll
                for (int j = 0; j < 2; j++)
                    ldsm2(bf[j], pB + (wn*16 + j*8 + (lane & 7))*STRB + ks*32 + ((lane >> 3) & 1)*16);
                #pragma unroll
                for (int i = 0; i < 2; i++)
                    #pragma unroll
                    for (int j = 0; j < 2; j++)
                        mma_bf16(acc[i][j], af[i], bf[j]);
            }
        }
    }

    int qr = lane >> 2, qc = (lane & 3)*2;
    float* base = g_part + ((size_t)chunk*32 + bh)*4096;
    #pragma unroll
    for (int i = 0; i < 2; i++) {
        #pragma unroll
        for (int half = 0; half < 2; half++) {
            int m = wm*32 + i*16 + qr + half*8;
            float* dst = base + (size_t)m*64 + wn*16 + qc;
            #pragma unroll
            for (int j = 0; j < 2; j++) {
                float2 v;
                v.x = acc[i][j][half*2+0];
                v.y = acc[i][j][half*2+1];
                *(float2*)(dst + j*8) = v;
            }
        }
    }
}

// ======================= small fp32 kernels (passed in round 2) =======================
__global__ void transpose_rb(const float* __restrict__ rb)
{
    __shared__ float t[32][33];
    int l0 = blockIdx.x * 32, d0 = blockIdx.y * 32;
    int tx = threadIdx.x, ty = threadIdx.y;
    #pragma unroll
    for (int r = 0; r < 32; r += 8)
        t[ty + r][tx] = rb[(size_t)(d0 + ty + r) * CL + l0 + tx];
    __syncthreads();
    #pragma unroll
    for (int r = 0; r < 32; r += 8)
        g_rbt[(size_t)(l0 + ty + r) * CD + d0 + tx] = t[tx][ty + r];
}

__global__ void offsets_k(const float* __restrict__ w2, const float* __restrict__ b2)
{
    __shared__ float tile[64 * 128];
    __shared__ float w2s[128];
    int tid = threadIdx.x;
    int bg = blockIdx.y;
    int lq0 = blockIdx.x * 128;
    w2s[tid] = w2[tid];
    float sum = 0.f;
    for (int half = 0; half < 2; half++) {
        __syncthreads();
        for (int idx = tid; idx < 64 * 128; idx += 128) {
            int ci = idx >> 7, li = idx & 127;
            int l = lq0 - 2 + li;
            tile[idx] = (l >= 0) ? g_o1[((size_t)bg * 128 + half * 64 + ci) * CL + l] : 0.f;
        }
        __syncthreads();
        for (int ci = 0; ci < 64; ci++) sum += w2s[half * 64 + ci] * tile[ci * 128 + tid];
    }
    g_offs[(size_t)bg * CL + lq0 + tid] = 5.f * tanhf(sum + b2[0]);
}

__global__ void sampler_k(const float* __restrict__ x)
{
    int blk = blockIdx.x;
    int b = blk >> 13, l = blk & (CL - 1);
    int tid = threadIdx.x;
    int d4 = tid * 4;
    int g = tid >> 5;
    float off = g_offs[(size_t)(b * 4 + g) * CL + l];
    float vg = (float)l + off;
    float gg = 2.f * vg / 8195.f - 1.f;
    float ps = ((gg + 1.f) * 8192.f - 1.f) * 0.5f;
    float p0 = floorf(ps);
    float w1 = ps - p0;
    int i0 = (int)p0, i1 = i0 + 1;
    float4 a = make_float4(0.f, 0.f, 0.f, 0.f);
    float4 c = make_float4(0.f, 0.f, 0.f, 0.f);
    if (i0 >= 0 && i0 < CL) a = *(const float4*)(x + ((size_t)b * CL + i0) * CD + d4);
    if (i1 >= 0 && i1 < CL) c = *(const float4*)(x + ((size_t)b * CL + i1) * CD + d4);
    float w0 = 1.f - w1;
    float4 rr;
    rr.x = a.x * w0 + c.x * w1;
    rr.y = a.y * w0 + c.y * w1;
    rr.z = a.z * w0 + c.z * w1;
    rr.w = a.w * w0 + c.w * w1;
    *(float4*)(g_xs + ((size_t)b * CL + l) * CD + d4) = rr;
}

__global__ void softmax_k()
{
    int bh = blockIdx.x, i = threadIdx.x;
    const float scale = 0.04419417382415922f;
    float v[64];
    for (int j = 0; j < 64; j++) {
        float s = 0.f;
        #pragma unroll
        for (int c = 0; c < 8; c++) s += g_part[((size_t)c * 32 + bh) * 4096 + i * 64 + j];
        v[j] = s * scale;
    }
    float mx = v[0];
    for (int j = 1; j < 64; j++) mx = fmaxf(mx, v[j]);
    float sum = 0.f;
    for (int j = 0; j < 64; j++) { v[j] = expf(v[j] - mx); sum += v[j]; }
    float inv = 1.f / sum;
    for (int j = 0; j < 64; j++) g_attn[(size_t)bh * 4096 + i * 64 + j] = v[j] * inv;
}

__global__ void weff_k(const float* __restrict__ Wout)
{
    __shared__ float As[64 * 64];
    int b = blockIdx.x, h = blockIdx.y, tid = threadIdx.x;
    for (int idx = tid; idx < 4096; idx += 256)
        As[idx] = g_attn[((size_t)(b * 8 + h)) * 4096 + idx];
    __syncthreads();
    for (int o = tid; o < CD; o += 256) {
        float wr[64];
        #pragma unroll
        for (int i = 0; i < 64; i++) wr[i] = Wout[(size_t)o * CD + h * 64 + i];
        for (int j = 0; j < 64; j++) {
            float s = 0.f;
            #pragma unroll
            for (int i = 0; i < 64; i++) s += wr[i] * As[i * 64 + j];
            g_weff[((size_t)b * CD + o) * CD + h * 64 + j] = s;
        }
    }
}

// ======================= launch =======================
extern "C" void kernel_launch(void* const* d_in, const int* in_sizes, int n_in,
                              void* d_out, int out_size)
{
    const float* x     = (const float*)d_in[0];
    const float* Wq    = (const float*)d_in[1];
    const float* bq    = (const float*)d_in[2];
    const float* Wk    = (const float*)d_in[3];
    const float* bk    = (const float*)d_in[4];
    const float* Wv    = (const float*)d_in[5];
    const float* bv    = (const float*)d_in[6];
    const float* Woff1 = (const float*)d_in[7];
    const float* boff1 = (const float*)d_in[8];
    const float* Woff2 = (const float*)d_in[9];
    const float* boff2 = (const float*)d_in[10];
    const float* relb  = (const float*)d_in[11];
    const float* Wout  = (const float*)d_in[12];
    const float* bout  = (const float*)d_in[13];
    float* out = (float*)d_out;

    cudaFuncSetAttribute(gemm_mma, cudaFuncAttributeMaxDynamicSharedMemorySize, GSMEM);
    cudaFuncSetAttribute(conv_mma, cudaFuncAttributeMaxDynamicSharedMemorySize, GSMEM);

    transpose_rb<<<dim3(CL/32, CD/32), dim3(32, 8)>>>(relb);
    gemm_mma<<<dim3(64, 4, CB), 256, GSMEM>>>(Wq, x, bq, nullptr, 0);        // q
    conv_mma<<<dim3(64, 16), 256, GSMEM>>>(Woff1, boff1);                    // offset conv1
    offsets_k<<<dim3(64, 16), 128>>>(Woff2, boff2);                          // conv2 + tanh
    sampler_k<<<CB*CL, 128>>>(x);                                            // bilinear gather
    gemm_mma<<<dim3(64, 4, CB), 256, GSMEM>>>(Wk, nullptr, bk, nullptr, 1);  // k
    gemm_mma<<<dim3(4, 64, CB), 256, GSMEM>>>(Wv, nullptr, bv, nullptr, 2);  // v (+rel_bias)
    scores_mma<<<dim3(32, 8), 256, 2*BUFS>>>();                              // q·kᵀ split-K
    softmax_k<<<32, 64>>>();                                                 // reduce+softmax
    weff_k<<<dim3(CB, 8), 256>>>(Wout);                                      // fold attn into Wout
    gemm_mma<<<dim3(4, 64, CB), 256, GSMEM>>>(nullptr, nullptr, bout, out, 3); // final
}

// round 6
// speedup vs baseline: 2.2355x; 1.1448x over previous
#include <cuda_runtime.h>
#include <cuda_bf16.h>
#include <cstdint>

#define CL 8192
#define CD 512
#define CB 4

// ---------------- bf16 split planes (hi + lo residual), device globals ----------------
__device__ __nv_bfloat16 g_xh [CB*CL*CD], g_xl [CB*CL*CD];   // x row-major (B*L, D)
__device__ __nv_bfloat16 g_xsh[CB*CL*CD], g_xsl[CB*CL*CD];   // sampled x row-major
__device__ __nv_bfloat16 g_qch[CB*CD*CL], g_qcl[CB*CD*CL];   // q chan-major (B*D, L)
__device__ __nv_bfloat16 g_kch[CB*CD*CL], g_kcl[CB*CD*CL];   // k chan-major
__device__ __nv_bfloat16 g_vth[CB*CL*CD], g_vtl[CB*CL*CD];   // v row-major
__device__ __nv_bfloat16 g_wqh[CD*CD], g_wql[CD*CD];
__device__ __nv_bfloat16 g_wkh[CD*CD], g_wkl[CD*CD];
__device__ __nv_bfloat16 g_wvh[CD*CD], g_wvl[CD*CD];
__device__ __nv_bfloat16 g_w1h[128*640], g_w1l[128*640];
__device__ __nv_bfloat16 g_weh[CB*CD*CD], g_wel[CB*CD*CD];   // folded attn+Wout
// fp32 scratch
__device__ float g_o1[16*128*CL];
__device__ float g_offs[16*CL];
__device__ float g_rbt[CL*CD];
__device__ float g_part[8*32*64*64];
__device__ float g_attn[32*64*64];

// ======================= helpers =======================
__device__ __forceinline__ uint32_t smem_u32(const void* p){
    uint32_t a;
    asm("{ .reg .u64 t; cvta.to.shared.u64 t, %1; cvt.u32.u64 %0, t; }" : "=r"(a) : "l"(p));
    return a;
}
__device__ __forceinline__ void mma_bf16(float* c, const uint32_t* a, const uint32_t* b){
    asm volatile("mma.sync.aligned.m16n8k16.row.col.f32.bf16.bf16.f32 "
        "{%0,%1,%2,%3}, {%4,%5,%6,%7}, {%8,%9}, {%0,%1,%2,%3};"
        : "+f"(c[0]), "+f"(c[1]), "+f"(c[2]), "+f"(c[3])
        : "r"(a[0]), "r"(a[1]), "r"(a[2]), "r"(a[3]), "r"(b[0]), "r"(b[1]));
}
__device__ __forceinline__ void ldsm4(uint32_t* r, uint32_t addr){
    asm volatile("ldmatrix.sync.aligned.m8n8.x4.shared.b16 {%0,%1,%2,%3}, [%4];"
        : "=r"(r[0]), "=r"(r[1]), "=r"(r[2]), "=r"(r[3]) : "r"(addr));
}
__device__ __forceinline__ void ldsm2(uint32_t* r, uint32_t addr){
    asm volatile("ldmatrix.sync.aligned.m8n8.x2.shared.b16 {%0,%1}, [%2];"
        : "=r"(r[0]), "=r"(r[1]) : "r"(addr));
}
__device__ __forceinline__ void cpa16(uint32_t dst, const void* src){
    asm volatile("cp.async.cg.shared.global [%0], [%1], 16;" :: "r"(dst), "l"(src));
}
#define CPA_COMMIT() asm volatile("cp.async.commit_group;" ::: "memory")
#define CPA_WAIT1()  asm volatile("cp.async.wait_group 1;" ::: "memory")
#define CPA_WAIT0()  asm volatile("cp.async.wait_group 0;" ::: "memory")

__device__ __forceinline__ void split2(float v0, float v1, __nv_bfloat16* hp, __nv_bfloat16* lp){
    __nv_bfloat162 h, l;
    h.x = __float2bfloat16(v0); h.y = __float2bfloat16(v1);
    l.x = __float2bfloat16(v0 - __bfloat162float(h.x));
    l.y = __float2bfloat16(v1 - __bfloat162float(h.y));
    *(__nv_bfloat162*)hp = h; *(__nv_bfloat162*)lp = l;
}

#define STRB 80                 // bytes per plane row (32 bf16 + pad)
#define PL   10240              // 128 rows * 80
#define BUF  40960              // Ahi,Alo,Bhi,Blo
#define GSMEM (2*BUF)

// fill one operand (hi+lo planes) via cp.async: ROWS x 32 bf16
template<int ROWS>
__device__ __forceinline__ void fill_op(uint32_t sdst, uint32_t plbytes,
    const __nv_bfloat16* Hp, const __nv_bfloat16* Lp,
    size_t row0, int ld, int kof, int tid)
{
    constexpr int IT = (ROWS*4)/256;
    #pragma unroll
    for (int i = 0; i < IT; i++) {
        int o = tid + i*256;
        int row = o >> 2, seg = o & 3;
        size_t g = (row0 + row)*(size_t)ld + kof + seg*8;
        cpa16(sdst + row*STRB + seg*16,           Hp + g);
        cpa16(sdst + plbytes + row*STRB + seg*16, Lp + g);
    }
}

// consume one Kc=32 chunk: 3 split products x 2 ksteps, warp tile 64x32
__device__ __forceinline__ void mma_chunk128(float acc[4][4][4], uint32_t s0, int wm, int wn, int lane){
    #pragma unroll
    for (int p = 0; p < 3; p++) {
        uint32_t pA = s0 + ((p == 2) ? PL : 0);
        uint32_t pB = s0 + 2*PL + ((p == 1) ? PL : 0);
        #pragma unroll
        for (int ks = 0; ks < 2; ks++) {
            uint32_t af[4][4], bf[4][2];
            #pragma unroll
            for (int i = 0; i < 4; i++)
                ldsm4(af[i], pA + (wm*64 + i*16 + (lane & 15))*STRB + ks*32 + (lane >> 4)*16);
            #pragma unroll
            for (int j = 0; j < 4; j++)
                ldsm2(bf[j], pB + (wn*32 + j*8 + (lane & 7))*STRB + ks*32 + ((lane >> 3) & 1)*16);
            #pragma unroll
            for (int i = 0; i < 4; i++)
                #pragma unroll
                for (int j = 0; j < 4; j++)
                    mma_bf16(acc[i][j], af[i], bf[j]);
        }
    }
}

// ======================= prep: fp32 -> hi/lo planes =======================
__global__ void cvt_planes(const float* __restrict__ src, int n4, int mode)
{
    __nv_bfloat16 *hi, *lo;
    switch (mode) {
        case 0:  hi = g_xh;  lo = g_xl;  break;
        case 1:  hi = g_wqh; lo = g_wql; break;
        case 2:  hi = g_wkh; lo = g_wkl; break;
        case 3:  hi = g_wvh; lo = g_wvl; break;
        default: hi = g_w1h; lo = g_w1l; break;
    }
    int i = blockIdx.x*256 + threadIdx.x;
    if (i >= n4) return;
    float4 v = ((const float4*)src)[i];
    split2(v.x, v.y, hi + i*4,     lo + i*4);
    split2(v.z, v.w, hi + i*4 + 2, lo + i*4 + 2);
}

// ======================= unified big GEMM =======================
// modes: 0 q=Wq·x -> qc planes chan-major; 1 k=Wk·xs -> kc planes;
//        2 v=xs·Wvᵀ (+bv+relb) -> vt planes; 3 out=vt·Weffᵀ (+bout) -> fp32 Out
__global__ __launch_bounds__(256, 2)
void gemm_mma(const float* __restrict__ bias, float* __restrict__ Out, int mode)
{
    extern __shared__ __align__(16) char smem[];
    uint32_t sb = smem_u32(smem);
    int tid = threadIdx.x, lane = tid & 31, wid = tid >> 5;
    int wm = wid >> 2, wn = wid & 3;
    int bx = blockIdx.x, by = blockIdx.y, bz = blockIdx.z;

    const __nv_bfloat16 *Ah, *Al, *Bh, *Bl;
    size_t arow0, brow0;
    int lda, ldb;
    if (mode == 0) {
        Ah = g_wqh; Al = g_wql; lda = CD; arow0 = (size_t)by*128;
        Bh = g_xh;  Bl = g_xl;  ldb = CD; brow0 = (size_t)bz*CL + bx*128;
    } else if (mode == 1) {
        Ah = g_wkh; Al = g_wkl; lda = CD; arow0 = (size_t)by*128;
        Bh = g_xsh; Bl = g_xsl; ldb = CD; brow0 = (size_t)bz*CL + bx*128;
    } else if (mode == 2) {
        Ah = g_xsh; Al = g_xsl; lda = CD; arow0 = (size_t)bz*CL + by*128;
        Bh = g_wvh; Bl = g_wvl; ldb = CD; brow0 = (size_t)bx*128;
    } else {
        Ah = g_vth; Al = g_vtl; lda = CD; arow0 = (size_t)bz*CL + by*128;
        Bh = g_weh; Bl = g_wel; ldb = CD; brow0 = (size_t)bz*CD + bx*128;
    }

    float acc[4][4][4] = {};

    // chunk 0 fill
    fill_op<128>(sb,          PL, Ah, Al, arow0, lda, 0, tid);
    fill_op<128>(sb + 2*PL,   PL, Bh, Bl, brow0, ldb, 0, tid);
    CPA_COMMIT();

    for (int ch = 0; ch < 16; ch++) {
        uint32_t cur = sb + (ch & 1)*BUF;
        if (ch + 1 < 16) {
            uint32_t nxt = sb + ((ch+1) & 1)*BUF;
            fill_op<128>(nxt,        PL, Ah, Al, arow0, lda, (ch+1)*32, tid);
            fill_op<128>(nxt + 2*PL, PL, Bh, Bl, brow0, ldb, (ch+1)*32, tid);
            CPA_COMMIT();
            CPA_WAIT1();
        } else {
            CPA_WAIT0();
        }
        __syncthreads();
        mma_chunk128(acc, cur, wm, wn, lane);
        __syncthreads();
    }

    int qr = lane >> 2, qc = (lane & 3)*2;
    if (mode <= 1) {
        __nv_bfloat16* Hp = mode ? g_kch : g_qch;
        __nv_bfloat16* Lp = mode ? g_kcl : g_qcl;
        #pragma unroll
        for (int i = 0; i < 4; i++)
            #pragma unroll
            for (int half = 0; half < 2; half++) {
                int m = by*128 + wm*64 + i*16 + qr + half*8;
                float bm = bias[m];
                size_t rowo = ((size_t)bz*CD + m)*CL + bx*128 + wn*32 + qc;
                #pragma unroll
                for (int j = 0; j < 4; j++)
                    split2(acc[i][j][half*2+0] + bm, acc[i][j][half*2+1] + bm,
                           Hp + rowo + j*8, Lp + rowo + j*8);
            }
    } else if (mode == 2) {
        #pragma unroll
        for (int i = 0; i < 4; i++)
            #pragma unroll
            for (int half = 0; half < 2; half++) {
                int lrow = by*128 + wm*64 + i*16 + qr + half*8;
                size_t rowo = ((size_t)bz*CL + lrow)*CD + bx*128 + wn*32 + qc;
                const float* bn = bias + bx*128 + wn*32 + qc;
                const float* rp = g_rbt + (size_t)lrow*CD + bx*128 + wn*32 + qc;
                #pragma unroll
                for (int j = 0; j < 4; j++)
                    split2(acc[i][j][half*2+0] + bn[j*8+0] + rp[j*8+0],
                           acc[i][j][half*2+1] + bn[j*8+1] + rp[j*8+1],
                           g_vth + rowo + j*8, g_vtl + rowo + j*8);
            }
    } else {
        #pragma unroll
        for (int i = 0; i < 4; i++)
            #pragma unroll
            for (int half = 0; half < 2; half++) {
                int lrow = by*128 + wm*64 + i*16 + qr + half*8;
                float* dst = Out + ((size_t)bz*CL + lrow)*CD + bx*128 + wn*32 + qc;
                const float* bn = bias + bx*128 + wn*32 + qc;
                #pragma unroll
                for (int j = 0; j < 4; j++) {
                    float2 v;
                    v.x = acc[i][j][half*2+0] + bn[j*8+0];
                    v.y = acc[i][j][half*2+1] + bn[j*8+1];
                    *(float2*)(dst + j*8) = v;
                }
            }
    }
}

// ======================= conv1 as im2col GEMM (K=640) =======================
__global__ __launch_bounds__(256, 2)
void conv_mma(const float* __restrict__ b1)
{
    extern __shared__ __align__(16) char smem[];
    uint32_t sb = smem_u32(smem);
    int tid = threadIdx.x, lane = tid & 31, wid = tid >> 5;
    int wm = wid >> 2, wn = wid & 3;
    int l0 = blockIdx.x * 128, bg = blockIdx.y;
    const __nv_bfloat16* qh = g_qch + (size_t)(bg*128)*CL;
    const __nv_bfloat16* ql = g_qcl + (size_t)(bg*128)*CL;
    int r = tid >> 1, c0 = (tid & 1)*16;

    float acc[4][4][4] = {};

    auto fillB = [&](char* s, int ch){
        #pragma unroll
        for (int c = 0; c < 16; c++) {
            int k = ch*32 + c0 + c;
            int ci = (k*205) >> 10;       // floor(k/5), k<640
            int t  = k - ci*5;
            int l  = l0 + r + t - 2;
            __nv_bfloat16 h, lo;
            if (l >= 0 && l < CL) { h = qh[(size_t)ci*CL + l]; lo = ql[(size_t)ci*CL + l]; }
            else { h = __float2bfloat16(0.f); lo = h; }
            *(__nv_bfloat16*)(s + 2*PL + r*STRB + (c0+c)*2) = h;
            *(__nv_bfloat16*)(s + 3*PL + r*STRB + (c0+c)*2) = lo;
        }
    };

    fill_op<128>(sb, PL, g_w1h, g_w1l, 0, 640, 0, tid);
    fillB(smem, 0);
    CPA_COMMIT();

    for (int ch = 0; ch < 20; ch++) {
        uint32_t cur = sb + (ch & 1)*BUF;
        if (ch + 1 < 20) {
            char* nx = smem + ((ch+1) & 1)*BUF;
            fill_op<128>(sb + ((ch+1) & 1)*BUF, PL, g_w1h, g_w1l, 0, 640, (ch+1)*32, tid);
            fillB(nx, ch+1);
            CPA_COMMIT();
            CPA_WAIT1();
        } else {
            CPA_WAIT0();
        }
        __syncthreads();
        mma_chunk128(acc, cur, wm, wn, lane);
        __syncthreads();
    }

    int qr = lane >> 2, qc = (lane & 3)*2;
    #pragma unroll
    for (int i = 0; i < 4; i++)
        #pragma unroll
        for (int half = 0; half < 2; half++) {
            int co = wm*64 + i*16 + qr + half*8;
            float bm = b1[co];
            float* dst = g_o1 + ((size_t)(bg*128 + co))*CL + l0 + wn*32 + qc;
            #pragma unroll
            for (int j = 0; j < 4; j++) {
                float2 v;
                v.x = acc[i][j][half*2+0] + bm;
                v.y = acc[i][j][half*2+1] + bm;
                *(float2*)(dst + j*8) = v;
            }
        }
}

// ======================= scores: C[64,64] = q·kᵀ over K=1024 L-chunk =======================
#define PS   5120
#define BUFS 20480
__global__ __launch_bounds__(256)
void scores_mma()
{
    extern __shared__ __align__(16) char smem[];
    uint32_t sb = smem_u32(smem);
    int tid = threadIdx.x, lane = tid & 31, wid = tid >> 5;
    int wm = wid >> 2, wn = wid & 3;
    int bh = blockIdx.x, chunk = blockIdx.y;
    size_t chbase = (size_t)(bh >> 3)*CD + (size_t)(bh & 7)*64;
    int kof0 = chunk*1024;

    float acc[2][2][4] = {};

    fill_op<64>(sb,          PS, g_qch, g_qcl, chbase, CL, kof0, tid);
    fill_op<64>(sb + 2*PS,   PS, g_kch, g_kcl, chbase, CL, kof0, tid);
    CPA_COMMIT();

    for (int ch = 0; ch < 32; ch++) {
        uint32_t s0 = sb + (ch & 1)*BUFS;
        if (ch + 1 < 32) {
            uint32_t nx = sb + ((ch+1) & 1)*BUFS;
            fill_op<64>(nx,        PS, g_qch, g_qcl, chbase, CL, kof0 + (ch+1)*32, tid);
            fill_op<64>(nx + 2*PS, PS, g_kch, g_kcl, chbase, CL, kof0 + (ch+1)*32, tid);
            CPA_COMMIT();
            CPA_WAIT1();
        } else {
            CPA_WAIT0();
        }
        __syncthreads();
        #pragma unroll
        for (int p = 0; p < 3; p++) {
            uint32_t pA = s0 + ((p == 2) ? PS : 0);
            uint32_t pB = s0 + 2*PS + ((p == 1) ? PS : 0);
            #pragma unroll
            for (int ks = 0; ks < 2; ks++) {
                uint32_t af[2][4], bf[2][2];
                #pragma unroll
                for (int i = 0; i < 2; i++)
                    ldsm4(af[i], pA + (wm*32 + i*16 + (lane & 15))*STRB + ks*32 + (lane >> 4)*16);
                #pragma unroll
                for (int j = 0; j < 2; j++)
                    ldsm2(bf[j], pB + (wn*16 + j*8 + (lane & 7))*STRB + ks*32 + ((lane >> 3) & 1)*16);
                #pragma unroll
                for (int i = 0; i < 2; i++)
                    #pragma unroll
                    for (int j = 0; j < 2; j++)
                        mma_bf16(acc[i][j], af[i], bf[j]);
            }
        }
        __syncthreads();
    }

    int qr = lane >> 2, qc = (lane & 3)*2;
    float* base = g_part + ((size_t)chunk*32 + bh)*4096;
    #pragma unroll
    for (int i = 0; i < 2; i++)
        #pragma unroll
        for (int half = 0; half < 2; half++) {
            int m = wm*32 + i*16 + qr + half*8;
            float* dst = base + (size_t)m*64 + wn*16 + qc;
            #pragma unroll
            for (int j = 0; j < 2; j++) {
                float2 v;
                v.x = acc[i][j][half*2+0];
                v.y = acc[i][j][half*2+1];
                *(float2*)(dst + j*8) = v;
            }
        }
}

// ======================= small kernels =======================
__global__ void transpose_rb(const float* __restrict__ rb)
{
    __shared__ float t[32][33];
    int l0 = blockIdx.x * 32, d0 = blockIdx.y * 32;
    int tx = threadIdx.x, ty = threadIdx.y;
    #pragma unroll
    for (int r = 0; r < 32; r += 8)
        t[ty + r][tx] = rb[(size_t)(d0 + ty + r) * CL + l0 + tx];
    __syncthreads();
    #pragma unroll
    for (int r = 0; r < 32; r += 8)
        g_rbt[(size_t)(l0 + ty + r) * CD + d0 + tx] = t[tx][ty + r];
}

__global__ void offsets_k(const float* __restrict__ w2, const float* __restrict__ b2)
{
    __shared__ float tile[64 * 128];
    __shared__ float w2s[128];
    int tid = threadIdx.x;
    int bg = blockIdx.y;
    int lq0 = blockIdx.x * 128;
    w2s[tid] = w2[tid];
    float sum = 0.f;
    for (int half = 0; half < 2; half++) {
        __syncthreads();
        for (int idx = tid; idx < 64 * 128; idx += 128) {
            int ci = idx >> 7, li = idx & 127;
            int l = lq0 - 2 + li;
            tile[idx] = (l >= 0) ? g_o1[((size_t)bg * 128 + half * 64 + ci) * CL + l] : 0.f;
        }
        __syncthreads();
        for (int ci = 0; ci < 64; ci++) sum += w2s[half * 64 + ci] * tile[ci * 128 + tid];
    }
    g_offs[(size_t)bg * CL + lq0 + tid] = 5.f * tanhf(sum + b2[0]);
}

__global__ void sampler_k(const float* __restrict__ x)
{
    int blk = blockIdx.x;
    int b = blk >> 13, l = blk & (CL - 1);
    int tid = threadIdx.x;
    int d4 = tid * 4;
    int g = tid >> 5;
    float off = g_offs[(size_t)(b * 4 + g) * CL + l];
    float vg = (float)l + off;
    float gg = 2.f * vg / 8195.f - 1.f;
    float ps = ((gg + 1.f) * 8192.f - 1.f) * 0.5f;
    float p0 = floorf(ps);
    float w1 = ps - p0;
    int i0 = (int)p0, i1 = i0 + 1;
    float4 a = make_float4(0.f, 0.f, 0.f, 0.f);
    float4 c = make_float4(0.f, 0.f, 0.f, 0.f);
    if (i0 >= 0 && i0 < CL) a = *(const float4*)(x + ((size_t)b * CL + i0) * CD + d4);
    if (i1 >= 0 && i1 < CL) c = *(const float4*)(x + ((size_t)b * CL + i1) * CD + d4);
    float w0 = 1.f - w1;
    size_t idx = ((size_t)b * CL + l) * CD + d4;
    split2(a.x*w0 + c.x*w1, a.y*w0 + c.y*w1, g_xsh + idx,     g_xsl + idx);
    split2(a.z*w0 + c.z*w1, a.w*w0 + c.w*w1, g_xsh + idx + 2, g_xsl + idx + 2);
}

__global__ void softmax_k()
{
    int bh = blockIdx.x, i = threadIdx.x;
    const float scale = 0.04419417382415922f;
    float v[64];
    for (int j = 0; j < 64; j++) {
        float s = 0.f;
        #pragma unroll
        for (int c = 0; c < 8; c++) s += g_part[((size_t)c * 32 + bh) * 4096 + i * 64 + j];
        v[j] = s * scale;
    }
    float mx = v[0];
    for (int j = 1; j < 64; j++) mx = fmaxf(mx, v[j]);
    float sum = 0.f;
    for (int j = 0; j < 64; j++) { v[j] = expf(v[j] - mx); sum += v[j]; }
    float inv = 1.f / sum;
    for (int j = 0; j < 64; j++) g_attn[(size_t)bh * 4096 + i * 64 + j] = v[j] * inv;
}

__global__ void weff_k(const float* __restrict__ Wout)
{
    __shared__ float As[64 * 64];
    int b = blockIdx.x, h = blockIdx.y, tid = threadIdx.x;
    for (int idx = tid; idx < 4096; idx += 256)
        As[idx] = g_attn[((size_t)(b * 8 + h)) * 4096 + idx];
    __syncthreads();
    for (int o = tid; o < CD; o += 256) {
        float wr[64];
        #pragma unroll
        for (int i = 0; i < 64; i++) wr[i] = Wout[(size_t)o * CD + h * 64 + i];
        for (int j = 0; j < 64; j++) {
            float s = 0.f;
            #pragma unroll
            for (int i = 0; i < 64; i++) s += wr[i] * As[i * 64 + j];
            size_t idx = ((size_t)b * CD + o) * CD + h * 64 + j;
            __nv_bfloat16 hh = __float2bfloat16(s);
            g_weh[idx] = hh;
            g_wel[idx] = __float2bfloat16(s - __bfloat162float(hh));
        }
    }
}

// ======================= launch =======================
extern "C" void kernel_launch(void* const* d_in, const int* in_sizes, int n_in,
                              void* d_out, int out_size)
{
    const float* x     = (const float*)d_in[0];
    const float* Wq    = (const float*)d_in[1];
    const float* bq    = (const float*)d_in[2];
    const float* Wk    = (const float*)d_in[3];
    const float* bk    = (const float*)d_in[4];
    const float* Wv    = (const float*)d_in[5];
    const float* bv    = (const float*)d_in[6];
    const float* Woff1 = (const float*)d_in[7];
    const float* boff1 = (const float*)d_in[8];
    const float* Woff2 = (const float*)d_in[9];
    const float* boff2 = (const float*)d_in[10];
    const float* relb  = (const float*)d_in[11];
    const float* Wout  = (const float*)d_in[12];
    const float* bout  = (const float*)d_in[13];
    float* out = (float*)d_out;

    cudaFuncSetAttribute(gemm_mma, cudaFuncAttributeMaxDynamicSharedMemorySize, GSMEM);
    cudaFuncSetAttribute(conv_mma, cudaFuncAttributeMaxDynamicSharedMemorySize, GSMEM);

    transpose_rb<<<dim3(CL/32, CD/32), dim3(32, 8)>>>(relb);
    cvt_planes<<<(CB*CL*CD/4 + 255)/256, 256>>>(x,     CB*CL*CD/4, 0);
    cvt_planes<<<(CD*CD/4 + 255)/256,    256>>>(Wq,    CD*CD/4,    1);
    cvt_planes<<<(CD*CD/4 + 255)/256,    256>>>(Wk,    CD*CD/4,    2);
    cvt_planes<<<(CD*CD/4 + 255)/256,    256>>>(Wv,    CD*CD/4,    3);
    cvt_planes<<<(128*640/4 + 255)/256,  256>>>(Woff1, 128*640/4,  4);

    gemm_mma<<<dim3(64, 4, CB), 256, GSMEM>>>(bq, nullptr, 0);       // q -> planes
    conv_mma<<<dim3(64, 16), 256, GSMEM>>>(boff1);                   // offset conv1
    offsets_k<<<dim3(64, 16), 128>>>(Woff2, boff2);                  // conv2 + tanh
    sampler_k<<<CB*CL, 128>>>(x);                                    // bilinear -> xs planes
    gemm_mma<<<dim3(64, 4, CB), 256, GSMEM>>>(bk, nullptr, 1);       // k -> planes
    gemm_mma<<<dim3(4, 64, CB), 256, GSMEM>>>(bv, nullptr, 2);       // v -> planes (+relb)
    scores_mma<<<dim3(32, 8), 256, 2*BUFS>>>();                      // q·kᵀ split-K
    softmax_k<<<32, 64>>>();
    weff_k<<<dim3(CB, 8), 256>>>(Wout);                              // fold attn into Wout
    gemm_mma<<<dim3(4, 64, CB), 256, GSMEM>>>(bout, out, 3);         // final -> fp32 out
}

// round 8
// speedup vs baseline: 3.0196x; 1.3507x over previous
#include <cuda_runtime.h>
#include <cuda_bf16.h>
#include <cuda_fp16.h>
#include <cstdint>

#define CL 8192
#define CD 512
#define CB 4

// ---------------- planes ----------------
// fp16 single (attention-weights path)
__device__ __half g_xf [CB*CL*CD];     // x row-major
__device__ __half g_xsf[CB*CL*CD];     // sampled x row-major
__device__ __half g_qf [CB*CD*CL];     // q chan-major
__device__ __half g_kf [CB*CD*CL];     // k chan-major
__device__ __half g_wqf[CD*CD], g_wkf[CD*CD], g_w1f[128*640];
// bf16 split (output path)
__device__ __nv_bfloat16 g_xsh[CB*CL*CD], g_xsl[CB*CL*CD];
__device__ __nv_bfloat16 g_vth[CB*CL*CD], g_vtl[CB*CL*CD];
__device__ __nv_bfloat16 g_wvh[CD*CD], g_wvl[CD*CD];
__device__ __nv_bfloat16 g_weh[CB*CD*CD], g_wel[CB*CD*CD];
// fp32 scratch
__device__ float g_o1[16*128*CL];
__device__ float g_offs[16*CL];
__device__ float g_rbt[CL*CD];
__device__ float g_part[8*32*64*64];
__device__ float g_attn[32*64*64];

// ======================= helpers =======================
__device__ __forceinline__ uint32_t smem_u32(const void* p){
    uint32_t a;
    asm("{ .reg .u64 t; cvta.to.shared.u64 t, %1; cvt.u32.u64 %0, t; }" : "=r"(a) : "l"(p));
    return a;
}
__device__ __forceinline__ void mma_bf16(float* c, const uint32_t* a, const uint32_t* b){
    asm volatile("mma.sync.aligned.m16n8k16.row.col.f32.bf16.bf16.f32 "
        "{%0,%1,%2,%3}, {%4,%5,%6,%7}, {%8,%9}, {%0,%1,%2,%3};"
        : "+f"(c[0]), "+f"(c[1]), "+f"(c[2]), "+f"(c[3])
        : "r"(a[0]), "r"(a[1]), "r"(a[2]), "r"(a[3]), "r"(b[0]), "r"(b[1]));
}
__device__ __forceinline__ void mma_f16(float* c, const uint32_t* a, const uint32_t* b){
    asm volatile("mma.sync.aligned.m16n8k16.row.col.f32.f16.f16.f32 "
        "{%0,%1,%2,%3}, {%4,%5,%6,%7}, {%8,%9}, {%0,%1,%2,%3};"
        : "+f"(c[0]), "+f"(c[1]), "+f"(c[2]), "+f"(c[3])
        : "r"(a[0]), "r"(a[1]), "r"(a[2]), "r"(a[3]), "r"(b[0]), "r"(b[1]));
}
__device__ __forceinline__ void ldsm4(uint32_t* r, uint32_t addr){
    asm volatile("ldmatrix.sync.aligned.m8n8.x4.shared.b16 {%0,%1,%2,%3}, [%4];"
        : "=r"(r[0]), "=r"(r[1]), "=r"(r[2]), "=r"(r[3]) : "r"(addr));
}
__device__ __forceinline__ void ldsm2(uint32_t* r, uint32_t addr){
    asm volatile("ldmatrix.sync.aligned.m8n8.x2.shared.b16 {%0,%1}, [%2];"
        : "=r"(r[0]), "=r"(r[1]) : "r"(addr));
}
__device__ __forceinline__ void cpa16(uint32_t dst, const void* src){
    asm volatile("cp.async.cg.shared.global [%0], [%1], 16;" :: "r"(dst), "l"(src));
}
#define CPA_COMMIT() asm volatile("cp.async.commit_group;" ::: "memory")
#define CPA_WAIT1()  asm volatile("cp.async.wait_group 1;" ::: "memory")
#define CPA_WAIT0()  asm volatile("cp.async.wait_group 0;" ::: "memory")

__device__ __forceinline__ void split2(float v0, float v1, __nv_bfloat16* hp, __nv_bfloat16* lp){
    __nv_bfloat162 h, l;
    h.x = __float2bfloat16(v0); h.y = __float2bfloat16(v1);
    l.x = __float2bfloat16(v0 - __bfloat162float(h.x));
    l.y = __float2bfloat16(v1 - __bfloat162float(h.y));
    *(__nv_bfloat162*)hp = h; *(__nv_bfloat162*)lp = l;
}

#define STRB 80                 // bytes per plane row (32 x 16-bit + pad)
#define PL   10240              // 128 rows * 80
#define BUF2 40960              // split: Ahi,Alo,Bhi,Blo
#define GSMEM (2*BUF2)          // 81920 (split GEMM)
#define BUF1 20480              // f16: A,B
#define FSMEM (2*BUF1)          // 40960 (f16 GEMM)

// fill one plane via cp.async: ROWS x 32 halves
template<int ROWS, typename T>
__device__ __forceinline__ void fill_p(uint32_t sdst, const T* P,
    size_t row0, int ld, int kof, int tid)
{
    constexpr int IT = (ROWS*4)/256;
    #pragma unroll
    for (int i = 0; i < IT; i++) {
        int o = tid + i*256;
        int row = o >> 2, seg = o & 3;
        cpa16(sdst + row*STRB + seg*16, P + (row0 + row)*(size_t)ld + kof + seg*8);
    }
}

// split 3-product chunk consumer (128x128 tile, warp 64x32)
__device__ __forceinline__ void mma_chunk3(float acc[4][4][4], uint32_t s0, int wm, int wn, int lane){
    #pragma unroll
    for (int p = 0; p < 3; p++) {
        uint32_t pA = s0 + ((p == 2) ? PL : 0);
        uint32_t pB = s0 + 2*PL + ((p == 1) ? PL : 0);
        #pragma unroll
        for (int ks = 0; ks < 2; ks++) {
            uint32_t af[4][4], bf[4][2];
            #pragma unroll
            for (int i = 0; i < 4; i++)
                ldsm4(af[i], pA + (wm*64 + i*16 + (lane & 15))*STRB + ks*32 + (lane >> 4)*16);
            #pragma unroll
            for (int j = 0; j < 4; j++)
                ldsm2(bf[j], pB + (wn*32 + j*8 + (lane & 7))*STRB + ks*32 + ((lane >> 3) & 1)*16);
            #pragma unroll
            for (int i = 0; i < 4; i++)
                #pragma unroll
                for (int j = 0; j < 4; j++)
                    mma_bf16(acc[i][j], af[i], bf[j]);
        }
    }
}
// fp16 single-product chunk consumer (128x128 tile, warp 64x32)
__device__ __forceinline__ void mma_chunk1(float acc[4][4][4], uint32_t s0, int wm, int wn, int lane){
    #pragma unroll
    for (int ks = 0; ks < 2; ks++) {
        uint32_t af[4][4], bf[4][2];
        #pragma unroll
        for (int i = 0; i < 4; i++)
            ldsm4(af[i], s0 + (wm*64 + i*16 + (lane & 15))*STRB + ks*32 + (lane >> 4)*16);
        #pragma unroll
        for (int j = 0; j < 4; j++)
            ldsm2(bf[j], s0 + PL + (wn*32 + j*8 + (lane & 7))*STRB + ks*32 + ((lane >> 3) & 1)*16);
        #pragma unroll
        for (int i = 0; i < 4; i++)
            #pragma unroll
            for (int j = 0; j < 4; j++)
                mma_f16(acc[i][j], af[i], bf[j]);
    }
}

// ======================= prep kernels =======================
__global__ void cvt_f16(const float* __restrict__ src, int n4, int mode)
{
    __half* dst;
    switch (mode) {
        case 0:  dst = g_xf;  break;
        case 1:  dst = g_wqf; break;
        case 2:  dst = g_wkf; break;
        default: dst = g_w1f; break;
    }
    int i = blockIdx.x*256 + threadIdx.x;
    if (i >= n4) return;
    float4 v = ((const float4*)src)[i];
    __half2 a = __floats2half2_rn(v.x, v.y);
    __half2 b = __floats2half2_rn(v.z, v.w);
    *(uint2*)(dst + i*4) = make_uint2(*(uint32_t*)&a, *(uint32_t*)&b);
}
__global__ void cvt_wv(const float* __restrict__ src)
{
    int i = blockIdx.x*256 + threadIdx.x;
    if (i >= CD*CD/4) return;
    float4 v = ((const float4*)src)[i];
    split2(v.x, v.y, g_wvh + i*4,     g_wvl + i*4);
    split2(v.z, v.w, g_wvh + i*4 + 2, g_wvl + i*4 + 2);
}

// ======================= fp16 single-product GEMM (q, k) =======================
// mode 0: q = Wq·x  -> g_qf chan-major.  mode 1: k = Wk·xs -> g_kf chan-major.
__global__ __launch_bounds__(256, 2)
void gemm_f16(const float* __restrict__ bias, int mode)
{
    extern __shared__ __align__(16) char smem[];
    uint32_t sb = smem_u32(smem);
    int tid = threadIdx.x, lane = tid & 31, wid = tid >> 5;
    int wm = wid >> 2, wn = wid & 3;
    int bx = blockIdx.x, by = blockIdx.y, bz = blockIdx.z;

    const __half* A = mode ? g_wkf : g_wqf;
    const __half* B = mode ? g_xsf : g_xf;
    size_t arow0 = (size_t)by*128;
    size_t brow0 = (size_t)bz*CL + bx*128;

    float acc[4][4][4] = {};

    fill_p<128>(sb,       A, arow0, CD, 0, tid);
    fill_p<128>(sb + PL,  B, brow0, CD, 0, tid);
    CPA_COMMIT();

    for (int ch = 0; ch < 16; ch++) {
        uint32_t cur = sb + (ch & 1)*BUF1;
        if (ch + 1 < 16) {
            uint32_t nxt = sb + ((ch+1) & 1)*BUF1;
            fill_p<128>(nxt,      A, arow0, CD, (ch+1)*32, tid);
            fill_p<128>(nxt + PL, B, brow0, CD, (ch+1)*32, tid);
            CPA_COMMIT();
            CPA_WAIT1();
        } else {
            CPA_WAIT0();
        }
        __syncthreads();
        mma_chunk1(acc, cur, wm, wn, lane);
        __syncthreads();
    }

    __half* Cp = mode ? g_kf : g_qf;
    int qr = lane >> 2, qc = (lane & 3)*2;
    #pragma unroll
    for (int i = 0; i < 4; i++)
        #pragma unroll
        for (int half = 0; half < 2; half++) {
            int m = by*128 + wm*64 + i*16 + qr + half*8;
            float bm = bias[m];
            size_t rowo = ((size_t)bz*CD + m)*CL + bx*128 + wn*32 + qc;
            #pragma unroll
            for (int j = 0; j < 4; j++) {
                __half2 h = __floats2half2_rn(acc[i][j][half*2+0] + bm,
                                              acc[i][j][half*2+1] + bm);
                *(__half2*)(Cp + rowo + j*8) = h;
            }
        }
}

// ======================= split 3-product GEMM (v, final) =======================
// mode 2: v = xs·Wvᵀ (+bv+relb) -> vt planes;  mode 3: out = vt·Weffᵀ (+bout) -> fp32 Out
__global__ __launch_bounds__(256, 2)
void gemm_split(const float* __restrict__ bias, float* __restrict__ Out, int mode)
{
    extern __shared__ __align__(16) char smem[];
    uint32_t sb = smem_u32(smem);
    int tid = threadIdx.x, lane = tid & 31, wid = tid >> 5;
    int wm = wid >> 2, wn = wid & 3;
    int bx = blockIdx.x, by = blockIdx.y, bz = blockIdx.z;

    const __nv_bfloat16 *Ah, *Al, *Bh, *Bl;
    size_t arow0, brow0;
    if (mode == 2) {
        Ah = g_xsh; Al = g_xsl; arow0 = (size_t)bz*CL + by*128;
        Bh = g_wvh; Bl = g_wvl; brow0 = (size_t)bx*128;
    } else {
        Ah = g_vth; Al = g_vtl; arow0 = (size_t)bz*CL + by*128;
        Bh = g_weh; Bl = g_wel; brow0 = (size_t)bz*CD + bx*128;
    }

    float acc[4][4][4] = {};

    fill_p<128>(sb,        Ah, arow0, CD, 0, tid);
    fill_p<128>(sb + PL,   Al, arow0, CD, 0, tid);
    fill_p<128>(sb + 2*PL, Bh, brow0, CD, 0, tid);
    fill_p<128>(sb + 3*PL, Bl, brow0, CD, 0, tid);
    CPA_COMMIT();

    for (int ch = 0; ch < 16; ch++) {
        uint32_t cur = sb + (ch & 1)*BUF2;
        if (ch + 1 < 16) {
            uint32_t nxt = sb + ((ch+1) & 1)*BUF2;
            fill_p<128>(nxt,        Ah, arow0, CD, (ch+1)*32, tid);
            fill_p<128>(nxt + PL,   Al, arow0, CD, (ch+1)*32, tid);
            fill_p<128>(nxt + 2*PL, Bh, brow0, CD, (ch+1)*32, tid);
            fill_p<128>(nxt + 3*PL, Bl, brow0, CD, (ch+1)*32, tid);
            CPA_COMMIT();
            CPA_WAIT1();
        } else {
            CPA_WAIT0();
        }
        __syncthreads();
        mma_chunk3(acc, cur, wm, wn, lane);
        __syncthreads();
    }

    int qr = lane >> 2, qc = (lane & 3)*2;
    if (mode == 2) {
        #pragma unroll
        for (int i = 0; i < 4; i++)
            #pragma unroll
            for (int half = 0; half < 2; half++) {
                int lrow = by*128 + wm*64 + i*16 + qr + half*8;
                size_t rowo = ((size_t)bz*CL + lrow)*CD + bx*128 + wn*32 + qc;
                const float* bn = bias + bx*128 + wn*32 + qc;
                const float* rp = g_rbt + (size_t)lrow*CD + bx*128 + wn*32 + qc;
                #pragma unroll
                for (int j = 0; j < 4; j++)
                    split2(acc[i][j][half*2+0] + bn[j*8+0] + rp[j*8+0],
                           acc[i][j][half*2+1] + bn[j*8+1] + rp[j*8+1],
                           g_vth + rowo + j*8, g_vtl + rowo + j*8);
            }
    } else {
        #pragma unroll
        for (int i = 0; i < 4; i++)
            #pragma unroll
            for (int half = 0; half < 2; half++) {
                int lrow = by*128 + wm*64 + i*16 + qr + half*8;
                float* dst = Out + ((size_t)bz*CL + lrow)*CD + bx*128 + wn*32 + qc;
                const float* bn = bias + bx*128 + wn*32 + qc;
                #pragma unroll
                for (int j = 0; j < 4; j++) {
                    float2 v;
                    v.x = acc[i][j][half*2+0] + bn[j*8+0];
                    v.y = acc[i][j][half*2+1] + bn[j*8+1];
                    *(float2*)(dst + j*8) = v;
                }
            }
    }
}

// ======================= conv1 im2col (fp16 single, K=640) =======================
__global__ __launch_bounds__(256, 2)
void conv_f16(const float* __restrict__ b1)
{
    extern __shared__ __align__(16) char smem[];
    uint32_t sb = smem_u32(smem);
    int tid = threadIdx.x, lane = tid & 31, wid = tid >> 5;
    int wm = wid >> 2, wn = wid & 3;
    int l0 = blockIdx.x * 128, bg = blockIdx.y;
    const __half* qp = g_qf + (size_t)(bg*128)*CL;
    int r = tid >> 1, c0 = (tid & 1)*16;

    float acc[4][4][4] = {};

    auto fillB = [&](char* s, int ch){
        #pragma unroll
        for (int c = 0; c < 16; c++) {
            int k = ch*32 + c0 + c;
            int ci = (k*205) >> 10;       // floor(k/5), k<640
            int t  = k - ci*5;
            int l  = l0 + r + t - 2;
            __half h = (l >= 0 && l < CL) ? qp[(size_t)ci*CL + l] : __float2half(0.f);
            *(__half*)(s + PL + r*STRB + (c0+c)*2) = h;
        }
    };

    fill_p<128>(sb, g_w1f, 0, 640, 0, tid);
    fillB(smem, 0);
    CPA_COMMIT();

    for (int ch = 0; ch < 20; ch++) {
        uint32_t cur = sb + (ch & 1)*BUF1;
        if (ch + 1 < 20) {
            char* nx = smem + ((ch+1) & 1)*BUF1;
            fill_p<128>(sb + ((ch+1) & 1)*BUF1, g_w1f, 0, 640, (ch+1)*32, tid);
            fillB(nx, ch+1);
            CPA_COMMIT();
            CPA_WAIT1();
        } else {
            CPA_WAIT0();
        }
        __syncthreads();
        mma_chunk1(acc, cur, wm, wn, lane);
        __syncthreads();
    }

    int qr = lane >> 2, qc = (lane & 3)*2;
    #pragma unroll
    for (int i = 0; i < 4; i++)
        #pragma unroll
        for (int half = 0; half < 2; half++) {
            int co = wm*64 + i*16 + qr + half*8;
            float bm = b1[co];
            float* dst = g_o1 + ((size_t)(bg*128 + co))*CL + l0 + wn*32 + qc;
            #pragma unroll
            for (int j = 0; j < 4; j++) {
                float2 v;
                v.x = acc[i][j][half*2+0] + bm;
                v.y = acc[i][j][half*2+1] + bm;
                *(float2*)(dst + j*8) = v;
            }
        }
}

// ======================= scores (fp16 single): C[64,64] = q·kᵀ over K=1024 =======================
#define PS    5120
#define SBUF1 10240
__global__ __launch_bounds__(256)
void scores_f16()
{
    extern __shared__ __align__(16) char smem[];
    uint32_t sb = smem_u32(smem);
    int tid = threadIdx.x, lane = tid & 31, wid = tid >> 5;
    int wm = wid >> 2, wn = wid & 3;
    int bh = blockIdx.x, chunk = blockIdx.y;
    size_t chbase = (size_t)(bh >> 3)*CD + (size_t)(bh & 7)*64;
    int kof0 = chunk*1024;

    float acc[2][2][4] = {};

    fill_p<64>(sb,      g_qf, chbase, CL, kof0, tid);
    fill_p<64>(sb + PS, g_kf, chbase, CL, kof0, tid);
    CPA_COMMIT();

    for (int ch = 0; ch < 32; ch++) {
        uint32_t s0 = sb + (ch & 1)*SBUF1;
        if (ch + 1 < 32) {
            uint32_t nx = sb + ((ch+1) & 1)*SBUF1;
            fill_p<64>(nx,      g_qf, chbase, CL, kof0 + (ch+1)*32, tid);
            fill_p<64>(nx + PS, g_kf, chbase, CL, kof0 + (ch+1)*32, tid);
            CPA_COMMIT();
            CPA_WAIT1();
        } else {
            CPA_WAIT0();
        }
        __syncthreads();
        #pragma unroll
        for (int ks = 0; ks < 2; ks++) {
            uint32_t af[2][4], bf[2][2];
            #pragma unroll
            for (int i = 0; i < 2; i++)
                ldsm4(af[i], s0 + (wm*32 + i*16 + (lane & 15))*STRB + ks*32 + (lane >> 4)*16);
            #pragma unroll
            for (int j = 0; j < 2; j++)
                ldsm2(bf[j], s0 + PS + (wn*16 + j*8 + (lane & 7))*STRB + ks*32 + ((lane >> 3) & 1)*16);
            #pragma unroll
            for (int i = 0; i < 2; i++)
                #pragma unroll
                for (int j = 0; j < 2; j++)
                    mma_f16(acc[i][j], af[i], bf[j]);
        }
        __syncthreads();
    }

    int qr = lane >> 2, qc = (lane & 3)*2;
    float* base = g_part + ((size_t)chunk*32 + bh)*4096;
    #pragma unroll
    for (int i = 0; i < 2; i++)
        #pragma unroll
        for (int half = 0; half < 2; half++) {
            int m = wm*32 + i*16 + qr + half*8;
            float* dst = base + (size_t)m*64 + wn*16 + qc;
            #pragma unroll
            for (int j = 0; j < 2; j++) {
                float2 v;
                v.x = acc[i][j][half*2+0];
                v.y = acc[i][j][half*2+1];
                *(float2*)(dst + j*8) = v;
            }
        }
}

// ======================= small kernels =======================
__global__ void transpose_rb(const float* __restrict__ rb)
{
    __shared__ float t[32][33];
    int l0 = blockIdx.x * 32, d0 = blockIdx.y * 32;
    int tx = threadIdx.x, ty = threadIdx.y;
    #pragma unroll
    for (int r = 0; r < 32; r += 8)
        t[ty + r][tx] = rb[(size_t)(d0 + ty + r) * CL + l0 + tx];
    __syncthreads();
    #pragma unroll
    for (int r = 0; r < 32; r += 8)
        g_rbt[(size_t)(l0 + ty + r) * CD + d0 + tx] = t[tx][ty + r];
}

__global__ void offsets_k(const float* __restrict__ w2, const float* __restrict__ b2)
{
    __shared__ float tile[64 * 128];
    __shared__ float w2s[128];
    int tid = threadIdx.x;
    int bg = blockIdx.y;
    int lq0 = blockIdx.x * 128;
    w2s[tid] = w2[tid];
    float sum = 0.f;
    for (int half = 0; half < 2; half++) {
        __syncthreads();
        for (int idx = tid; idx < 64 * 128; idx += 128) {
            int ci = idx >> 7, li = idx & 127;
            int l = lq0 - 2 + li;
            tile[idx] = (l >= 0) ? g_o1[((size_t)bg * 128 + half * 64 + ci) * CL + l] : 0.f;
        }
        __syncthreads();
        for (int ci = 0; ci < 64; ci++) sum += w2s[half * 64 + ci] * tile[ci * 128 + tid];
    }
    g_offs[(size_t)bg * CL + lq0 + tid] = 5.f * tanhf(sum + b2[0]);
}

__global__ void sampler_k(const float* __restrict__ x)
{
    int blk = blockIdx.x;
    int b = blk >> 13, l = blk & (CL - 1);
    int tid = threadIdx.x;
    int d4 = tid * 4;
    int g = tid >> 5;
    float off = g_offs[(size_t)(b * 4 + g) * CL + l];
    float vg = (float)l + off;
    float gg = 2.f * vg / 8195.f - 1.f;
    float ps = ((gg + 1.f) * 8192.f - 1.f) * 0.5f;
    float p0 = floorf(ps);
    float w1 = ps - p0;
    int i0 = (int)p0, i1 = i0 + 1;
    float4 a = make_float4(0.f, 0.f, 0.f, 0.f);
    float4 c = make_float4(0.f, 0.f, 0.f, 0.f);
    if (i0 >= 0 && i0 < CL) a = *(const float4*)(x + ((size_t)b * CL + i0) * CD + d4);
    if (i1 >= 0 && i1 < CL) c = *(const float4*)(x + ((size_t)b * CL + i1) * CD + d4);
    float w0 = 1.f - w1;
    float s0 = a.x*w0 + c.x*w1, s1 = a.y*w0 + c.y*w1;
    float s2 = a.z*w0 + c.z*w1, s3 = a.w*w0 + c.w*w1;
    size_t idx = ((size_t)b * CL + l) * CD + d4;
    split2(s0, s1, g_xsh + idx,     g_xsl + idx);
    split2(s2, s3, g_xsh + idx + 2, g_xsl + idx + 2);
    __half2 h0 = __floats2half2_rn(s0, s1);
    __half2 h1 = __floats2half2_rn(s2, s3);
    *(uint2*)(g_xsf + idx) = make_uint2(*(uint32_t*)&h0, *(uint32_t*)&h1);
}

__global__ void softmax_k()
{
    int bh = blockIdx.x, i = threadIdx.x;
    const float scale = 0.04419417382415922f;
    float v[64];
    for (int j = 0; j < 64; j++) {
        float s = 0.f;
        #pragma unroll
        for (int c = 0; c < 8; c++) s += g_part[((size_t)c * 32 + bh) * 4096 + i * 64 + j];
        v[j] = s * scale;
    }
    float mx = v[0];
    for (int j = 1; j < 64; j++) mx = fmaxf(mx, v[j]);
    float sum = 0.f;
    for (int j = 0; j < 64; j++) { v[j] = expf(v[j] - mx); sum += v[j]; }
    float inv = 1.f / sum;
    for (int j = 0; j < 64; j++) g_attn[(size_t)bh * 4096 + i * 64 + j] = v[j] * inv;
}

__global__ void weff_k(const float* __restrict__ Wout)
{
    __shared__ float As[64 * 64];
    int b = blockIdx.x, h = blockIdx.y, tid = threadIdx.x;
    for (int idx = tid; idx < 4096; idx += 256)
        As[idx] = g_attn[((size_t)(b * 8 + h)) * 4096 + idx];
    __syncthreads();
    for (int o = tid; o < CD; o += 256) {
        float wr[64];
        #pragma unroll
        for (int i = 0; i < 64; i++) wr[i] = Wout[(size_t)o * CD + h * 64 + i];
        for (int j = 0; j < 64; j++) {
            float s = 0.f;
            #pragma unroll
            for (int i = 0; i < 64; i++) s += wr[i] * As[i * 64 + j];
            size_t idx = ((size_t)b * CD + o) * CD + h * 64 + j;
            __nv_bfloat16 hh = __float2bfloat16(s);
            g_weh[idx] = hh;
            g_wel[idx] = __float2bfloat16(s - __bfloat162float(hh));
        }
    }
}

// ======================= launch =======================
extern "C" void kernel_launch(void* const* d_in, const int* in_sizes, int n_in,
                              void* d_out, int out_size)
{
    const float* x     = (const float*)d_in[0];
    const float* Wq    = (const float*)d_in[1];
    const float* bq    = (const float*)d_in[2];
    const float* Wk    = (const float*)d_in[3];
    const float* bk    = (const float*)d_in[4];
    const float* Wv    = (const float*)d_in[5];
    const float* bv    = (const float*)d_in[6];
    const float* Woff1 = (const float*)d_in[7];
    const float* boff1 = (const float*)d_in[8];
    const float* Woff2 = (const float*)d_in[9];
    const float* boff2 = (const float*)d_in[10];
    const float* relb  = (const float*)d_in[11];
    const float* Wout  = (const float*)d_in[12];
    const float* bout  = (const float*)d_in[13];
    float* out = (float*)d_out;

    cudaFuncSetAttribute(gemm_split, cudaFuncAttributeMaxDynamicSharedMemorySize, GSMEM);
    cudaFuncSetAttribute(gemm_f16,   cudaFuncAttributeMaxDynamicSharedMemorySize, FSMEM);
    cudaFuncSetAttribute(conv_f16,   cudaFuncAttributeMaxDynamicSharedMemorySize, FSMEM);

    transpose_rb<<<dim3(CL/32, CD/32), dim3(32, 8)>>>(relb);
    cvt_f16<<<(CB*CL*CD/4 + 255)/256, 256>>>(x,     CB*CL*CD/4, 0);
    cvt_f16<<<(CD*CD/4 + 255)/256,    256>>>(Wq,    CD*CD/4,    1);
    cvt_f16<<<(CD*CD/4 + 255)/256,    256>>>(Wk,    CD*CD/4,    2);
    cvt_f16<<<(128*640/4 + 255)/256,  256>>>(Woff1, 128*640/4,  3);
    cvt_wv <<<(CD*CD/4 + 255)/256,    256>>>(Wv);

    gemm_f16<<<dim3(64, 4, CB), 256, FSMEM>>>(bq, 0);        // q -> fp16 chan-major
    conv_f16<<<dim3(64, 16), 256, FSMEM>>>(boff1);           // offset conv1
    offsets_k<<<dim3(64, 16), 128>>>(Woff2, boff2);          // conv2 + tanh
    sampler_k<<<CB*CL, 128>>>(x);                            // bilinear -> xs planes
    gemm_f16<<<dim3(64, 4, CB), 256, FSMEM>>>(bk, 1);        // k -> fp16 chan-major
    gemm_split<<<dim3(4, 64, CB), 256, GSMEM>>>(bv, nullptr, 2);   // v (+relb)
    scores_f16<<<dim3(32, 8), 256, 2*SBUF1>>>();             // q·kᵀ split-K
    softmax_k<<<32, 64>>>();
    weff_k<<<dim3(CB, 8), 256>>>(Wout);                      // fold attn into Wout
    gemm_split<<<dim3(4, 64, CB), 256, GSMEM>>>(bout, out, 3);     // final -> fp32 out
}

// round 9
// speedup vs baseline: 3.8094x; 1.2616x over previous
#include <cuda_runtime.h>
#include <cuda_bf16.h>
#include <cuda_fp16.h>
#include <cstdint>

#define CL 8192
#define CD 512
#define CB 4

// ---------------- fp16 planes ----------------
__device__ __half g_xf [CB*CL*CD];                 // x row-major (single)
__device__ __half g_xsh[CB*CL*CD], g_xsl[CB*CL*CD];// sampled x row-major (split)
__device__ __half g_qf [CB*CD*CL];                 // q chan-major (single)
__device__ __half g_kf [CB*CD*CL];                 // k chan-major (single)
__device__ __half g_vh [CB*CL*CD], g_vl [CB*CL*CD];// v row-major (split)
__device__ __half g_wqf[CD*CD], g_wkf[CD*CD], g_wvf[CD*CD];
__device__ __half g_wef[CB*CD*CD];                 // folded attn+Wout (single)
// fp32 scratch
__device__ float g_offs[16*CL];
__device__ float g_rbt[CL*CD];
__device__ float g_part[8*32*64*64];
__device__ float g_attn[32*64*64];
__device__ float g_weff1[640];                     // composed offset conv kernel
__device__ float g_beff;                           // composed bias
__device__ float g_b2v;                            // raw b2 (lq<2 case)

// ======================= helpers =======================
__device__ __forceinline__ uint32_t smem_u32(const void* p){
    uint32_t a;
    asm("{ .reg .u64 t; cvta.to.shared.u64 t, %1; cvt.u32.u64 %0, t; }" : "=r"(a) : "l"(p));
    return a;
}
__device__ __forceinline__ void mma_f16(float* c, const uint32_t* a, const uint32_t* b){
    asm volatile("mma.sync.aligned.m16n8k16.row.col.f32.f16.f16.f32 "
        "{%0,%1,%2,%3}, {%4,%5,%6,%7}, {%8,%9}, {%0,%1,%2,%3};"
        : "+f"(c[0]), "+f"(c[1]), "+f"(c[2]), "+f"(c[3])
        : "r"(a[0]), "r"(a[1]), "r"(a[2]), "r"(a[3]), "r"(b[0]), "r"(b[1]));
}
__device__ __forceinline__ void ldsm4(uint32_t* r, uint32_t addr){
    asm volatile("ldmatrix.sync.aligned.m8n8.x4.shared.b16 {%0,%1,%2,%3}, [%4];"
        : "=r"(r[0]), "=r"(r[1]), "=r"(r[2]), "=r"(r[3]) : "r"(addr));
}
__device__ __forceinline__ void ldsm2(uint32_t* r, uint32_t addr){
    asm volatile("ldmatrix.sync.aligned.m8n8.x2.shared.b16 {%0,%1}, [%2];"
        : "=r"(r[0]), "=r"(r[1]) : "r"(addr));
}
__device__ __forceinline__ void cpa16(uint32_t dst, const void* src){
    asm volatile("cp.async.cg.shared.global [%0], [%1], 16;" :: "r"(dst), "l"(src));
}
#define CPA_COMMIT() asm volatile("cp.async.commit_group;" ::: "memory")
#define CPA_WAIT1()  asm volatile("cp.async.wait_group 1;" ::: "memory")
#define CPA_WAIT0()  asm volatile("cp.async.wait_group 0;" ::: "memory")

__device__ __forceinline__ void splith(float v0, float v1, __half* hp, __half* lp){
    __half h0 = __float2half_rn(v0), h1 = __float2half_rn(v1);
    __half l0 = __float2half_rn(v0 - __half2float(h0));
    __half l1 = __float2half_rn(v1 - __half2float(h1));
    __half2 hh; hh.x = h0; hh.y = h1;
    __half2 ll; ll.x = l0; ll.y = l1;
    *(__half2*)hp = hh; *(__half2*)lp = ll;
}

#define STRB 80                 // bytes per plane row (32 halves + pad)
#define PL   10240              // 128 rows * 80
#define BUF1 20480              // f16 single: A,B
#define FSMEM (2*BUF1)
#define BUF3 30720              // 2-prod: Ah,Al,B
#define HSMEM (2*BUF3)

// fill one plane via cp.async: ROWS x 32 halves
template<int ROWS, typename T>
__device__ __forceinline__ void fill_p(uint32_t sdst, const T* P,
    size_t row0, int ld, int kof, int tid)
{
    constexpr int IT = (ROWS*4)/256;
    #pragma unroll
    for (int i = 0; i < IT; i++) {
        int o = tid + i*256;
        int row = o >> 2, seg = o & 3;
        cpa16(sdst + row*STRB + seg*16, P + (row0 + row)*(size_t)ld + kof + seg*8);
    }
}

// fp16 single-product chunk (128x128 tile, warp 64x32)
__device__ __forceinline__ void mma_chunk1(float acc[4][4][4], uint32_t s0, int wm, int wn, int lane){
    #pragma unroll
    for (int ks = 0; ks < 2; ks++) {
        uint32_t af[4][4], bf[4][2];
        #pragma unroll
        for (int i = 0; i < 4; i++)
            ldsm4(af[i], s0 + (wm*64 + i*16 + (lane & 15))*STRB + ks*32 + (lane >> 4)*16);
        #pragma unroll
        for (int j = 0; j < 4; j++)
            ldsm2(bf[j], s0 + PL + (wn*32 + j*8 + (lane & 7))*STRB + ks*32 + ((lane >> 3) & 1)*16);
        #pragma unroll
        for (int i = 0; i < 4; i++)
            #pragma unroll
            for (int j = 0; j < 4; j++)
                mma_f16(acc[i][j], af[i], bf[j]);
    }
}
// fp16 2-product chunk: (Ah+Al)·B
__device__ __forceinline__ void mma_chunk2(float acc[4][4][4], uint32_t s0, int wm, int wn, int lane){
    #pragma unroll
    for (int p = 0; p < 2; p++) {
        uint32_t pA = s0 + p*PL;
        uint32_t pB = s0 + 2*PL;
        #pragma unroll
        for (int ks = 0; ks < 2; ks++) {
            uint32_t af[4][4], bf[4][2];
            #pragma unroll
            for (int i = 0; i < 4; i++)
                ldsm4(af[i], pA + (wm*64 + i*16 + (lane & 15))*STRB + ks*32 + (lane >> 4)*16);
            #pragma unroll
            for (int j = 0; j < 4; j++)
                ldsm2(bf[j], pB + (wn*32 + j*8 + (lane & 7))*STRB + ks*32 + ((lane >> 3) & 1)*16);
            #pragma unroll
            for (int i = 0; i < 4; i++)
                #pragma unroll
                for (int j = 0; j < 4; j++)
                    mma_f16(acc[i][j], af[i], bf[j]);
        }
    }
}

// ======================= prep kernels =======================
__global__ void cvt_f16(const float* __restrict__ src, int n4, int mode)
{
    __half* dst;
    switch (mode) {
        case 0:  dst = g_xf;  break;
        case 1:  dst = g_wqf; break;
        case 2:  dst = g_wkf; break;
        default: dst = g_wvf; break;
    }
    int i = blockIdx.x*256 + threadIdx.x;
    if (i >= n4) return;
    float4 v = ((const float4*)src)[i];
    __half2 a = __floats2half2_rn(v.x, v.y);
    __half2 b = __floats2half2_rn(v.z, v.w);
    *(uint2*)(dst + i*4) = make_uint2(*(uint32_t*)&a, *(uint32_t*)&b);
}

// compose conv2(conv1(.)): Weff[ci][t] = sum_co w2[co]*W1[co][ci][t]; beff = b2 + sum w2*b1
__global__ void compose_off(const float* __restrict__ W1, const float* __restrict__ b1,
                            const float* __restrict__ w2, const float* __restrict__ b2)
{
    int tid = threadIdx.x;
    if (tid < 640) {
        float s = 0.f;
        #pragma unroll 4
        for (int co = 0; co < 128; co++) s += w2[co] * W1[co*640 + tid];
        g_weff1[tid] = s;
    }
    if (tid == 0) {
        float b = b2[0];
        for (int co = 0; co < 128; co++) b += w2[co] * b1[co];
        g_beff = b;
        g_b2v = b2[0];
    }
}

// ======================= fp16 single GEMM (q, k) =======================
__global__ __launch_bounds__(256, 2)
void gemm_f16(const float* __restrict__ bias, int mode)
{
    extern __shared__ __align__(16) char smem[];
    uint32_t sb = smem_u32(smem);
    int tid = threadIdx.x, lane = tid & 31, wid = tid >> 5;
    int wm = wid >> 2, wn = wid & 3;
    int bx = blockIdx.x, by = blockIdx.y, bz = blockIdx.z;

    const __half* A = mode ? g_wkf : g_wqf;
    const __half* B = mode ? g_xsh : g_xf;
    size_t arow0 = (size_t)by*128;
    size_t brow0 = (size_t)bz*CL + bx*128;

    float acc[4][4][4] = {};

    fill_p<128>(sb,       A, arow0, CD, 0, tid);
    fill_p<128>(sb + PL,  B, brow0, CD, 0, tid);
    CPA_COMMIT();

    for (int ch = 0; ch < 16; ch++) {
        uint32_t cur = sb + (ch & 1)*BUF1;
        if (ch + 1 < 16) {
            uint32_t nxt = sb + ((ch+1) & 1)*BUF1;
            fill_p<128>(nxt,      A, arow0, CD, (ch+1)*32, tid);
            fill_p<128>(nxt + PL, B, brow0, CD, (ch+1)*32, tid);
            CPA_COMMIT();
            CPA_WAIT1();
        } else {
            CPA_WAIT0();
        }
        __syncthreads();
        mma_chunk1(acc, cur, wm, wn, lane);
        __syncthreads();
    }

    __half* Cp = mode ? g_kf : g_qf;
    int qr = lane >> 2, qc = (lane & 3)*2;
    #pragma unroll
    for (int i = 0; i < 4; i++)
        #pragma unroll
        for (int half = 0; half < 2; half++) {
            int m = by*128 + wm*64 + i*16 + qr + half*8;
            float bm = bias[m];
            size_t rowo = ((size_t)bz*CD + m)*CL + bx*128 + wn*32 + qc;
            #pragma unroll
            for (int j = 0; j < 4; j++) {
                __half2 h = __floats2half2_rn(acc[i][j][half*2+0] + bm,
                                              acc[i][j][half*2+1] + bm);
                *(__half2*)(Cp + rowo + j*8) = h;
            }
        }
}

// ======================= fp16 2-product GEMM (v, final) =======================
// mode 0: v = xs_split·Wvᵀ (+bv+relb) -> v fp16 split
// mode 1: out = v_split·Weffᵀ (+bout) -> fp32 Out
__global__ __launch_bounds__(256, 2)
void gemm_h2(const float* __restrict__ bias, float* __restrict__ Out, int mode)
{
    extern __shared__ __align__(16) char smem[];
    uint32_t sb = smem_u32(smem);
    int tid = threadIdx.x, lane = tid & 31, wid = tid >> 5;
    int wm = wid >> 2, wn = wid & 3;
    int bx = blockIdx.x, by = blockIdx.y, bz = blockIdx.z;

    const __half *Ah, *Al, *B;
    size_t arow0 = (size_t)bz*CL + by*128, brow0;
    if (mode == 0) { Ah = g_xsh; Al = g_xsl; B = g_wvf; brow0 = (size_t)bx*128; }
    else           { Ah = g_vh;  Al = g_vl;  B = g_wef; brow0 = (size_t)bz*CD + bx*128; }

    float acc[4][4][4] = {};

    fill_p<128>(sb,        Ah, arow0, CD, 0, tid);
    fill_p<128>(sb + PL,   Al, arow0, CD, 0, tid);
    fill_p<128>(sb + 2*PL, B,  brow0, CD, 0, tid);
    CPA_COMMIT();

    for (int ch = 0; ch < 16; ch++) {
        uint32_t cur = sb + (ch & 1)*BUF3;
        if (ch + 1 < 16) {
            uint32_t nxt = sb + ((ch+1) & 1)*BUF3;
            fill_p<128>(nxt,        Ah, arow0, CD, (ch+1)*32, tid);
            fill_p<128>(nxt + PL,   Al, arow0, CD, (ch+1)*32, tid);
            fill_p<128>(nxt + 2*PL, B,  brow0, CD, (ch+1)*32, tid);
            CPA_COMMIT();
            CPA_WAIT1();
        } else {
            CPA_WAIT0();
        }
        __syncthreads();
        mma_chunk2(acc, cur, wm, wn, lane);
        __syncthreads();
    }

    int qr = lane >> 2, qc = (lane & 3)*2;
    if (mode == 0) {
        #pragma unroll
        for (int i = 0; i < 4; i++)
            #pragma unroll
            for (int half = 0; half < 2; half++) {
                int lrow = by*128 + wm*64 + i*16 + qr + half*8;
                size_t rowo = ((size_t)bz*CL + lrow)*CD + bx*128 + wn*32 + qc;
                const float* bn = bias + bx*128 + wn*32 + qc;
                const float* rp = g_rbt + (size_t)lrow*CD + bx*128 + wn*32 + qc;
                #pragma unroll
                for (int j = 0; j < 4; j++)
                    splith(acc[i][j][half*2+0] + bn[j*8+0] + rp[j*8+0],
                           acc[i][j][half*2+1] + bn[j*8+1] + rp[j*8+1],
                           g_vh + rowo + j*8, g_vl + rowo + j*8);
            }
    } else {
        #pragma unroll
        for (int i = 0; i < 4; i++)
            #pragma unroll
            for (int half = 0; half < 2; half++) {
                int lrow = by*128 + wm*64 + i*16 + qr + half*8;
                float* dst = Out + ((size_t)bz*CL + lrow)*CD + bx*128 + wn*32 + qc;
                const float* bn = bias + bx*128 + wn*32 + qc;
                #pragma unroll
                for (int j = 0; j < 4; j++) {
                    float2 v;
                    v.x = acc[i][j][half*2+0] + bn[j*8+0];
                    v.y = acc[i][j][half*2+1] + bn[j*8+1];
                    *(float2*)(dst + j*8) = v;
                }
            }
    }
}

// ======================= fused offsets (composed conv1+conv2 + tanh) =======================
// offs[bg][lq] = 5*tanh(beff + sum_{cj,t} Weff[cj][t] * qpad[cj][lq-4+t])  (lq>=2)
//             = 5*tanh(b2)                                                 (lq<2)
__global__ void offsets_fused()
{
    __shared__ __half tile[128*132];
    __shared__ float wsh[640];
    int tid = threadIdx.x;           // 128
    int bg = blockIdx.y;
    int l0 = blockIdx.x * 128;

    for (int i = tid; i < 640; i += 128) wsh[i] = g_weff1[i];
    for (int idx = tid; idx < 128*132; idx += 128) {
        int cj = idx / 132, j = idx - cj*132;
        int l = l0 - 4 + j;
        tile[idx] = (l >= 0) ? g_qf[((size_t)(bg*128 + cj))*CL + l] : __float2half(0.f);
    }
    __syncthreads();

    int lq = l0 + tid;
    float sum;
    if (lq >= 2) {
        sum = g_beff;
        #pragma unroll 4
        for (int cj = 0; cj < 128; cj++) {
            const __half* tr = tile + cj*132 + tid;
            const float* wr = wsh + cj*5;
            #pragma unroll
            for (int t = 0; t < 5; t++)
                sum += wr[t] * __half2float(tr[t]);
        }
    } else {
        sum = g_b2v;
    }
    g_offs[(size_t)bg * CL + lq] = 5.f * tanhf(sum);
}

// ======================= scores (fp16 single): C[64,64] = q·kᵀ over K=1024 =======================
#define PS    5120
#define SBUF1 10240
__global__ __launch_bounds__(256)
void scores_f16()
{
    extern __shared__ __align__(16) char smem[];
    uint32_t sb = smem_u32(smem);
    int tid = threadIdx.x, lane = tid & 31, wid = tid >> 5;
    int wm = wid >> 2, wn = wid & 3;
    int bh = blockIdx.x, chunk = blockIdx.y;
    size_t chbase = (size_t)(bh >> 3)*CD + (size_t)(bh & 7)*64;
    int kof0 = chunk*1024;

    float acc[2][2][4] = {};

    fill_p<64>(sb,      g_qf, chbase, CL, kof0, tid);
    fill_p<64>(sb + PS, g_kf, chbase, CL, kof0, tid);
    CPA_COMMIT();

    for (int ch = 0; ch < 32; ch++) {
        uint32_t s0 = sb + (ch & 1)*SBUF1;
        if (ch + 1 < 32) {
            uint32_t nx = sb + ((ch+1) & 1)*SBUF1;
            fill_p<64>(nx,      g_qf, chbase, CL, kof0 + (ch+1)*32, tid);
            fill_p<64>(nx + PS, g_kf, chbase, CL, kof0 + (ch+1)*32, tid);
            CPA_COMMIT();
            CPA_WAIT1();
        } else {
            CPA_WAIT0();
        }
        __syncthreads();
        #pragma unroll
        for (int ks = 0; ks < 2; ks++) {
            uint32_t af[2][4], bf[2][2];
            #pragma unroll
            for (int i = 0; i < 2; i++)
                ldsm4(af[i], s0 + (wm*32 + i*16 + (lane & 15))*STRB + ks*32 + (lane >> 4)*16);
            #pragma unroll
            for (int j = 0; j < 2; j++)
                ldsm2(bf[j], s0 + PS + (wn*16 + j*8 + (lane & 7))*STRB + ks*32 + ((lane >> 3) & 1)*16);
            #pragma unroll
            for (int i = 0; i < 2; i++)
                #pragma unroll
                for (int j = 0; j < 2; j++)
                    mma_f16(acc[i][j], af[i], bf[j]);
        }
        __syncthreads();
    }

    int qr = lane >> 2, qc = (lane & 3)*2;
    float* base = g_part + ((size_t)chunk*32 + bh)*4096;
    #pragma unroll
    for (int i = 0; i < 2; i++)
        #pragma unroll
        for (int half = 0; half < 2; half++) {
            int m = wm*32 + i*16 + qr + half*8;
            float* dst = base + (size_t)m*64 + wn*16 + qc;
            #pragma unroll
            for (int j = 0; j < 2; j++) {
                float2 v;
                v.x = acc[i][j][half*2+0];
                v.y = acc[i][j][half*2+1];
                *(float2*)(dst + j*8) = v;
            }
        }
}

// ======================= small kernels =======================
__global__ void transpose_rb(const float* __restrict__ rb)
{
    __shared__ float t[32][33];
    int l0 = blockIdx.x * 32, d0 = blockIdx.y * 32;
    int tx = threadIdx.x, ty = threadIdx.y;
    #pragma unroll
    for (int r = 0; r < 32; r += 8)
        t[ty + r][tx] = rb[(size_t)(d0 + ty + r) * CL + l0 + tx];
    __syncthreads();
    #pragma unroll
    for (int r = 0; r < 32; r += 8)
        g_rbt[(size_t)(l0 + ty + r) * CD + d0 + tx] = t[tx][ty + r];
}

__global__ void sampler_k(const float* __restrict__ x)
{
    int blk = blockIdx.x;
    int b = blk >> 13, l = blk & (CL - 1);
    int tid = threadIdx.x;
    int d4 = tid * 4;
    int g = tid >> 5;
    float off = g_offs[(size_t)(b * 4 + g) * CL + l];
    float vg = (float)l + off;
    float gg = 2.f * vg / 8195.f - 1.f;
    float ps = ((gg + 1.f) * 8192.f - 1.f) * 0.5f;
    float p0 = floorf(ps);
    float w1 = ps - p0;
    int i0 = (int)p0, i1 = i0 + 1;
    float4 a = make_float4(0.f, 0.f, 0.f, 0.f);
    float4 c = make_float4(0.f, 0.f, 0.f, 0.f);
    if (i0 >= 0 && i0 < CL) a = *(const float4*)(x + ((size_t)b * CL + i0) * CD + d4);
    if (i1 >= 0 && i1 < CL) c = *(const float4*)(x + ((size_t)b * CL + i1) * CD + d4);
    float w0 = 1.f - w1;
    float s0 = a.x*w0 + c.x*w1, s1 = a.y*w0 + c.y*w1;
    float s2 = a.z*w0 + c.z*w1, s3 = a.w*w0 + c.w*w1;
    size_t idx = ((size_t)b * CL + l) * CD + d4;
    splith(s0, s1, g_xsh + idx,     g_xsl + idx);
    splith(s2, s3, g_xsh + idx + 2, g_xsl + idx + 2);
}

__global__ void softmax_k()
{
    int bh = blockIdx.x, i = threadIdx.x;
    const float scale = 0.04419417382415922f;
    float v[64];
    for (int j = 0; j < 64; j++) {
        float s = 0.f;
        #pragma unroll
        for (int c = 0; c < 8; c++) s += g_part[((size_t)c * 32 + bh) * 4096 + i * 64 + j];
        v[j] = s * scale;
    }
    float mx = v[0];
    for (int j = 1; j < 64; j++) mx = fmaxf(mx, v[j]);
    float sum = 0.f;
    for (int j = 0; j < 64; j++) { v[j] = expf(v[j] - mx); sum += v[j]; }
    float inv = 1.f / sum;
    for (int j = 0; j < 64; j++) g_attn[(size_t)bh * 4096 + i * 64 + j] = v[j] * inv;
}

__global__ void weff_k(const float* __restrict__ Wout)
{
    __shared__ float As[64 * 64];
    int b = blockIdx.x, h = blockIdx.y, tid = threadIdx.x;
    for (int idx = tid; idx < 4096; idx += 256)
        As[idx] = g_attn[((size_t)(b * 8 + h)) * 4096 + idx];
    __syncthreads();
    for (int o = tid; o < CD; o += 256) {
        float wr[64];
        #pragma unroll
        for (int i = 0; i < 64; i++) wr[i] = Wout[(size_t)o * CD + h * 64 + i];
        for (int j = 0; j < 64; j++) {
            float s = 0.f;
            #pragma unroll
            for (int i = 0; i < 64; i++) s += wr[i] * As[i * 64 + j];
            g_wef[((size_t)b * CD + o) * CD + h * 64 + j] = __float2half_rn(s);
        }
    }
}

// ======================= launch =======================
extern "C" void kernel_launch(void* const* d_in, const int* in_sizes, int n_in,
                              void* d_out, int out_size)
{
    const float* x     = (const float*)d_in[0];
    const float* Wq    = (const float*)d_in[1];
    const float* bq    = (const float*)d_in[2];
    const float* Wk    = (const float*)d_in[3];
    const float* bk    = (const float*)d_in[4];
    const float* Wv    = (const float*)d_in[5];
    const float* bv    = (const float*)d_in[6];
    const float* Woff1 = (const float*)d_in[7];
    const float* boff1 = (const float*)d_in[8];
    const float* Woff2 = (const float*)d_in[9];
    const float* boff2 = (const float*)d_in[10];
    const float* relb  = (const float*)d_in[11];
    const float* Wout  = (const float*)d_in[12];
    const float* bout  = (const float*)d_in[13];
    float* out = (float*)d_out;

    cudaFuncSetAttribute(gemm_f16, cudaFuncAttributeMaxDynamicSharedMemorySize, FSMEM);
    cudaFuncSetAttribute(gemm_h2,  cudaFuncAttributeMaxDynamicSharedMemorySize, HSMEM);

    transpose_rb<<<dim3(CL/32, CD/32), dim3(32, 8)>>>(relb);
    cvt_f16<<<(CB*CL*CD/4 + 255)/256, 256>>>(x,  CB*CL*CD/4, 0);
    cvt_f16<<<(CD*CD/4 + 255)/256,    256>>>(Wq, CD*CD/4,    1);
    cvt_f16<<<(CD*CD/4 + 255)/256,    256>>>(Wk, CD*CD/4,    2);
    cvt_f16<<<(CD*CD/4 + 255)/256,    256>>>(Wv, CD*CD/4,    3);
    compose_off<<<1, 640>>>(Woff1, boff1, Woff2, boff2);

    gemm_f16<<<dim3(64, 4, CB), 256, FSMEM>>>(bq, 0);        // q -> fp16 chan-major
    offsets_fused<<<dim3(64, 16), 128>>>();                  // composed conv1+conv2+tanh
    sampler_k<<<CB*CL, 128>>>(x);                            // bilinear -> xs fp16 split
    gemm_f16<<<dim3(64, 4, CB), 256, FSMEM>>>(bk, 1);        // k -> fp16 chan-major
    gemm_h2<<<dim3(4, 64, CB), 256, HSMEM>>>(bv, nullptr, 0);// v (+relb) -> fp16 split
    scores_f16<<<dim3(32, 8), 256, 2*SBUF1>>>();             // q·kᵀ split-K
    softmax_k<<<32, 64>>>();
    weff_k<<<dim3(CB, 8), 256>>>(Wout);                      // fold attn into Wout -> fp16
    gemm_h2<<<dim3(4, 64, CB), 256, HSMEM>>>(bout, out, 1);  // final -> fp32 out
}

// round 10
// speedup vs baseline: 3.8313x; 1.0057x over previous
#include <cuda_runtime.h>
#include <cuda_bf16.h>
#include <cuda_fp16.h>
#include <cstdint>

#define CL 8192
#define CD 512
#define CB 4

// ---------------- fp16 planes ----------------
__device__ __half g_xf [CB*CL*CD];                 // x row-major (single)
__device__ __half g_xsh[CB*CL*CD], g_xsl[CB*CL*CD];// sampled x row-major (split)
__device__ __half g_qf [CB*CD*CL];                 // q chan-major (single)
__device__ __half g_kf [CB*CD*CL];                 // k chan-major (single)
__device__ __half g_vh [CB*CL*CD], g_vl [CB*CL*CD];// v row-major (split)
__device__ __half g_wqf[CD*CD], g_wkf[CD*CD], g_wvf[CD*CD];
__device__ __half g_wef[CB*CD*CD];                 // folded attn+Wout (single)
// fp32 scratch
__device__ float g_offs[16*CL];
__device__ float g_rbt[CL*CD];
__device__ float g_part[8*32*64*64];
__device__ float g_attn[32*64*64];
__device__ float g_weff1[640];                     // composed offset conv kernel
__device__ float g_beff;                           // composed bias
__device__ float g_b2v;                            // raw b2 (lq<2 case)

// ======================= helpers =======================
__device__ __forceinline__ uint32_t smem_u32(const void* p){
    uint32_t a;
    asm("{ .reg .u64 t; cvta.to.shared.u64 t, %1; cvt.u32.u64 %0, t; }" : "=r"(a) : "l"(p));
    return a;
}
__device__ __forceinline__ void mma_f16(float* c, const uint32_t* a, const uint32_t* b){
    asm volatile("mma.sync.aligned.m16n8k16.row.col.f32.f16.f16.f32 "
        "{%0,%1,%2,%3}, {%4,%5,%6,%7}, {%8,%9}, {%0,%1,%2,%3};"
        : "+f"(c[0]), "+f"(c[1]), "+f"(c[2]), "+f"(c[3])
        : "r"(a[0]), "r"(a[1]), "r"(a[2]), "r"(a[3]), "r"(b[0]), "r"(b[1]));
}
__device__ __forceinline__ void ldsm4(uint32_t* r, uint32_t addr){
    asm volatile("ldmatrix.sync.aligned.m8n8.x4.shared.b16 {%0,%1,%2,%3}, [%4];"
        : "=r"(r[0]), "=r"(r[1]), "=r"(r[2]), "=r"(r[3]) : "r"(addr));
}
__device__ __forceinline__ void ldsm2(uint32_t* r, uint32_t addr){
    asm volatile("ldmatrix.sync.aligned.m8n8.x2.shared.b16 {%0,%1}, [%2];"
        : "=r"(r[0]), "=r"(r[1]) : "r"(addr));
}
__device__ __forceinline__ void cpa16(uint32_t dst, const void* src){
    asm volatile("cp.async.cg.shared.global [%0], [%1], 16;" :: "r"(dst), "l"(src));
}
#define CPA_COMMIT() asm volatile("cp.async.commit_group;" ::: "memory")
#define CPA_WAIT1()  asm volatile("cp.async.wait_group 1;" ::: "memory")
#define CPA_WAIT0()  asm volatile("cp.async.wait_group 0;" ::: "memory")

__device__ __forceinline__ void splith(float v0, float v1, __half* hp, __half* lp){
    __half h0 = __float2half_rn(v0), h1 = __float2half_rn(v1);
    __half l0 = __float2half_rn(v0 - __half2float(h0));
    __half l1 = __float2half_rn(v1 - __half2float(h1));
    __half2 hh; hh.x = h0; hh.y = h1;
    __half2 ll; ll.x = l0; ll.y = l1;
    *(__half2*)hp = hh; *(__half2*)lp = ll;
}

#define STRB 80                 // bytes per plane row (32 halves + pad)
#define PL   10240              // 128 rows * 80
#define BUF1 20480              // f16 single: A,B
#define FSMEM (3*BUF1)          // 3-stage
#define BUF3 30720              // 2-prod: Ah,Al,B
#define HSMEM (3*BUF3)          // 3-stage

// fill one plane via cp.async: ROWS x 32 halves
template<int ROWS, typename T>
__device__ __forceinline__ void fill_p(uint32_t sdst, const T* P,
    size_t row0, int ld, int kof, int tid)
{
    constexpr int IT = (ROWS*4)/256;
    #pragma unroll
    for (int i = 0; i < IT; i++) {
        int o = tid + i*256;
        int row = o >> 2, seg = o & 3;
        cpa16(sdst + row*STRB + seg*16, P + (row0 + row)*(size_t)ld + kof + seg*8);
    }
}

// fp16 single-product chunk (128x128 tile, warp 64x32)
__device__ __forceinline__ void mma_chunk1(float acc[4][4][4], uint32_t s0, int wm, int wn, int lane){
    #pragma unroll
    for (int ks = 0; ks < 2; ks++) {
        uint32_t af[4][4], bf[4][2];
        #pragma unroll
        for (int i = 0; i < 4; i++)
            ldsm4(af[i], s0 + (wm*64 + i*16 + (lane & 15))*STRB + ks*32 + (lane >> 4)*16);
        #pragma unroll
        for (int j = 0; j < 4; j++)
            ldsm2(bf[j], s0 + PL + (wn*32 + j*8 + (lane & 7))*STRB + ks*32 + ((lane >> 3) & 1)*16);
        #pragma unroll
        for (int i = 0; i < 4; i++)
            #pragma unroll
            for (int j = 0; j < 4; j++)
                mma_f16(acc[i][j], af[i], bf[j]);
    }
}
// fp16 2-product chunk: (Ah+Al)·B
__device__ __forceinline__ void mma_chunk2(float acc[4][4][4], uint32_t s0, int wm, int wn, int lane){
    #pragma unroll
    for (int p = 0; p < 2; p++) {
        uint32_t pA = s0 + p*PL;
        uint32_t pB = s0 + 2*PL;
        #pragma unroll
        for (int ks = 0; ks < 2; ks++) {
            uint32_t af[4][4], bf[4][2];
            #pragma unroll
            for (int i = 0; i < 4; i++)
                ldsm4(af[i], pA + (wm*64 + i*16 + (lane & 15))*STRB + ks*32 + (lane >> 4)*16);
            #pragma unroll
            for (int j = 0; j < 4; j++)
                ldsm2(bf[j], pB + (wn*32 + j*8 + (lane & 7))*STRB + ks*32 + ((lane >> 3) & 1)*16);
            #pragma unroll
            for (int i = 0; i < 4; i++)
                #pragma unroll
                for (int j = 0; j < 4; j++)
                    mma_f16(acc[i][j], af[i], bf[j]);
        }
    }
}

// ======================= prep kernels =======================
__global__ void cvt_f16(const float* __restrict__ src, int n4, int mode)
{
    __half* dst;
    switch (mode) {
        case 0:  dst = g_xf;  break;
        case 1:  dst = g_wqf; break;
        case 2:  dst = g_wkf; break;
        default: dst = g_wvf; break;
    }
    int i = blockIdx.x*256 + threadIdx.x;
    if (i >= n4) return;
    float4 v = ((const float4*)src)[i];
    __half2 a = __floats2half2_rn(v.x, v.y);
    __half2 b = __floats2half2_rn(v.z, v.w);
    *(uint2*)(dst + i*4) = make_uint2(*(uint32_t*)&a, *(uint32_t*)&b);
}

// compose conv2(conv1(.)): Weff[ci][t] = sum_co w2[co]*W1[co][ci][t]; beff = b2 + sum w2*b1
__global__ void compose_off(const float* __restrict__ W1, const float* __restrict__ b1,
                            const float* __restrict__ w2, const float* __restrict__ b2)
{
    int tid = threadIdx.x;
    if (tid < 640) {
        float s = 0.f;
        #pragma unroll 4
        for (int co = 0; co < 128; co++) s += w2[co] * W1[co*640 + tid];
        g_weff1[tid] = s;
    }
    if (tid == 0) {
        float b = b2[0];
        for (int co = 0; co < 128; co++) b += w2[co] * b1[co];
        g_beff = b;
        g_b2v = b2[0];
    }
}

// ======================= fp16 single GEMM (q, k) — 3-stage pipeline =======================
__global__ __launch_bounds__(256, 2)
void gemm_f16(const float* __restrict__ bias, int mode)
{
    extern __shared__ __align__(16) char smem[];
    uint32_t sb = smem_u32(smem);
    int tid = threadIdx.x, lane = tid & 31, wid = tid >> 5;
    int wm = wid >> 2, wn = wid & 3;
    int bx = blockIdx.x, by = blockIdx.y, bz = blockIdx.z;

    const __half* A = mode ? g_wkf : g_wqf;
    const __half* B = mode ? g_xsh : g_xf;
    size_t arow0 = (size_t)by*128;
    size_t brow0 = (size_t)bz*CL + bx*128;

    float acc[4][4][4] = {};

    fill_p<128>(sb,              A, arow0, CD, 0,  tid);
    fill_p<128>(sb + PL,         B, brow0, CD, 0,  tid);
    CPA_COMMIT();
    fill_p<128>(sb + BUF1,       A, arow0, CD, 32, tid);
    fill_p<128>(sb + BUF1 + PL,  B, brow0, CD, 32, tid);
    CPA_COMMIT();

    for (int ch = 0; ch < 16; ch++) {
        if (ch + 1 < 16) CPA_WAIT1(); else CPA_WAIT0();
        __syncthreads();
        if (ch + 2 < 16) {
            uint32_t nx = sb + ((ch+2) % 3)*BUF1;
            fill_p<128>(nx,      A, arow0, CD, (ch+2)*32, tid);
            fill_p<128>(nx + PL, B, brow0, CD, (ch+2)*32, tid);
            CPA_COMMIT();
        }
        mma_chunk1(acc, sb + (ch % 3)*BUF1, wm, wn, lane);
    }

    __half* Cp = mode ? g_kf : g_qf;
    int qr = lane >> 2, qc = (lane & 3)*2;
    #pragma unroll
    for (int i = 0; i < 4; i++)
        #pragma unroll
        for (int half = 0; half < 2; half++) {
            int m = by*128 + wm*64 + i*16 + qr + half*8;
            float bm = bias[m];
            size_t rowo = ((size_t)bz*CD + m)*CL + bx*128 + wn*32 + qc;
            #pragma unroll
            for (int j = 0; j < 4; j++) {
                __half2 h = __floats2half2_rn(acc[i][j][half*2+0] + bm,
                                              acc[i][j][half*2+1] + bm);
                *(__half2*)(Cp + rowo + j*8) = h;
            }
        }
}

// ======================= fp16 2-product GEMM (v, final) — 3-stage pipeline =======================
// mode 0: v = xs_split·Wvᵀ (+bv+relb) -> v fp16 split
// mode 1: out = v_split·Weffᵀ (+bout) -> fp32 Out
__global__ __launch_bounds__(256, 2)
void gemm_h2(const float* __restrict__ bias, float* __restrict__ Out, int mode)
{
    extern __shared__ __align__(16) char smem[];
    uint32_t sb = smem_u32(smem);
    int tid = threadIdx.x, lane = tid & 31, wid = tid >> 5;
    int wm = wid >> 2, wn = wid & 3;
    int bx = blockIdx.x, by = blockIdx.y, bz = blockIdx.z;

    const __half *Ah, *Al, *B;
    size_t arow0 = (size_t)bz*CL + by*128, brow0;
    if (mode == 0) { Ah = g_xsh; Al = g_xsl; B = g_wvf; brow0 = (size_t)bx*128; }
    else           { Ah = g_vh;  Al = g_vl;  B = g_wef; brow0 = (size_t)bz*CD + bx*128; }

    float acc[4][4][4] = {};

    fill_p<128>(sb,               Ah, arow0, CD, 0,  tid);
    fill_p<128>(sb + PL,          Al, arow0, CD, 0,  tid);
    fill_p<128>(sb + 2*PL,        B,  brow0, CD, 0,  tid);
    CPA_COMMIT();
    fill_p<128>(sb + BUF3,        Ah, arow0, CD, 32, tid);
    fill_p<128>(sb + BUF3 + PL,   Al, arow0, CD, 32, tid);
    fill_p<128>(sb + BUF3 + 2*PL, B,  brow0, CD, 32, tid);
    CPA_COMMIT();

    for (int ch = 0; ch < 16; ch++) {
        if (ch + 1 < 16) CPA_WAIT1(); else CPA_WAIT0();
        __syncthreads();
        if (ch + 2 < 16) {
            uint32_t nx = sb + ((ch+2) % 3)*BUF3;
            fill_p<128>(nx,        Ah, arow0, CD, (ch+2)*32, tid);
            fill_p<128>(nx + PL,   Al, arow0, CD, (ch+2)*32, tid);
            fill_p<128>(nx + 2*PL, B,  brow0, CD, (ch+2)*32, tid);
            CPA_COMMIT();
        }
        mma_chunk2(acc, sb + (ch % 3)*BUF3, wm, wn, lane);
    }

    int qr = lane >> 2, qc = (lane & 3)*2;
    if (mode == 0) {
        #pragma unroll
        for (int i = 0; i < 4; i++)
            #pragma unroll
            for (int half = 0; half < 2; half++) {
                int lrow = by*128 + wm*64 + i*16 + qr + half*8;
                size_t rowo = ((size_t)bz*CL + lrow)*CD + bx*128 + wn*32 + qc;
                const float* bn = bias + bx*128 + wn*32 + qc;
                const float* rp = g_rbt + (size_t)lrow*CD + bx*128 + wn*32 + qc;
                #pragma unroll
                for (int j = 0; j < 4; j++)
                    splith(acc[i][j][half*2+0] + bn[j*8+0] + rp[j*8+0],
                           acc[i][j][half*2+1] + bn[j*8+1] + rp[j*8+1],
                           g_vh + rowo + j*8, g_vl + rowo + j*8);
            }
    } else {
        #pragma unroll
        for (int i = 0; i < 4; i++)
            #pragma unroll
            for (int half = 0; half < 2; half++) {
                int lrow = by*128 + wm*64 + i*16 + qr + half*8;
                float* dst = Out + ((size_t)bz*CL + lrow)*CD + bx*128 + wn*32 + qc;
                const float* bn = bias + bx*128 + wn*32 + qc;
                #pragma unroll
                for (int j = 0; j < 4; j++) {
                    float2 v;
                    v.x = acc[i][j][half*2+0] + bn[j*8+0];
                    v.y = acc[i][j][half*2+1] + bn[j*8+1];
                    *(float2*)(dst + j*8) = v;
                }
            }
    }
}

// ======================= fused offsets (composed conv1+conv2 + tanh) =======================
__global__ void offsets_fused()
{
    __shared__ __half tile[128*132];
    __shared__ float wsh[640];
    int tid = threadIdx.x;           // 128
    int bg = blockIdx.y;
    int l0 = blockIdx.x * 128;

    for (int i = tid; i < 640; i += 128) wsh[i] = g_weff1[i];
    for (int idx = tid; idx < 128*132; idx += 128) {
        int cj = idx / 132, j = idx - cj*132;
        int l = l0 - 4 + j;
        tile[idx] = (l >= 0) ? g_qf[((size_t)(bg*128 + cj))*CL + l] : __float2half(0.f);
    }
    __syncthreads();

    int lq = l0 + tid;
    float sum;
    if (lq >= 2) {
        sum = g_beff;
        #pragma unroll 4
        for (int cj = 0; cj < 128; cj++) {
            const __half* tr = tile + cj*132 + tid;
            const float* wr = wsh + cj*5;
            #pragma unroll
            for (int t = 0; t < 5; t++)
                sum += wr[t] * __half2float(tr[t]);
        }
    } else {
        sum = g_b2v;
    }
    g_offs[(size_t)bg * CL + lq] = 5.f * tanhf(sum);
}

// ======================= scores (fp16 single) — 3-stage pipeline =======================
#define PS    5120
#define SBUF1 10240
#define SSMEM (3*SBUF1)
__global__ __launch_bounds__(256)
void scores_f16()
{
    extern __shared__ __align__(16) char smem[];
    uint32_t sb = smem_u32(smem);
    int tid = threadIdx.x, lane = tid & 31, wid = tid >> 5;
    int wm = wid >> 2, wn = wid & 3;
    int bh = blockIdx.x, chunk = blockIdx.y;
    size_t chbase = (size_t)(bh >> 3)*CD + (size_t)(bh & 7)*64;
    int kof0 = chunk*1024;

    float acc[2][2][4] = {};

    fill_p<64>(sb,              g_qf, chbase, CL, kof0,      tid);
    fill_p<64>(sb + PS,         g_kf, chbase, CL, kof0,      tid);
    CPA_COMMIT();
    fill_p<64>(sb + SBUF1,      g_qf, chbase, CL, kof0 + 32, tid);
    fill_p<64>(sb + SBUF1 + PS, g_kf, chbase, CL, kof0 + 32, tid);
    CPA_COMMIT();

    for (int ch = 0; ch < 32; ch++) {
        if (ch + 1 < 32) CPA_WAIT1(); else CPA_WAIT0();
        __syncthreads();
        if (ch + 2 < 32) {
            uint32_t nx = sb + ((ch+2) % 3)*SBUF1;
            fill_p<64>(nx,      g_qf, chbase, CL, kof0 + (ch+2)*32, tid);
            fill_p<64>(nx + PS, g_kf, chbase, CL, kof0 + (ch+2)*32, tid);
            CPA_COMMIT();
        }
        uint32_t s0 = sb + (ch % 3)*SBUF1;
        #pragma unroll
        for (int ks = 0; ks < 2; ks++) {
            uint32_t af[2][4], bf[2][2];
            #pragma unroll
            for (int i = 0; i < 2; i++)
                ldsm4(af[i], s0 + (wm*32 + i*16 + (lane & 15))*STRB + ks*32 + (lane >> 4)*16);
            #pragma unroll
            for (int j = 0; j < 2; j++)
                ldsm2(bf[j], s0 + PS + (wn*16 + j*8 + (lane & 7))*STRB + ks*32 + ((lane >> 3) & 1)*16);
            #pragma unroll
            for (int i = 0; i < 2; i++)
                #pragma unroll
                for (int j = 0; j < 2; j++)
                    mma_f16(acc[i][j], af[i], bf[j]);
        }
    }

    int qr = lane >> 2, qc = (lane & 3)*2;
    float* base = g_part + ((size_t)chunk*32 + bh)*4096;
    #pragma unroll
    for (int i = 0; i < 2; i++)
        #pragma unroll
        for (int half = 0; half < 2; half++) {
            int m = wm*32 + i*16 + qr + half*8;
            float* dst = base + (size_t)m*64 + wn*16 + qc;
            #pragma unroll
            for (int j = 0; j < 2; j++) {
                float2 v;
                v.x = acc[i][j][half*2+0];
                v.y = acc[i][j][half*2+1];
                *(float2*)(dst + j*8) = v;
            }
        }
}

// ======================= small kernels =======================
__global__ void transpose_rb(const float* __restrict__ rb)
{
    __shared__ float t[32][33];
    int l0 = blockIdx.x * 32, d0 = blockIdx.y * 32;
    int tx = threadIdx.x, ty = threadIdx.y;
    #pragma unroll
    for (int r = 0; r < 32; r += 8)
        t[ty + r][tx] = rb[(size_t)(d0 + ty + r) * CL + l0 + tx];
    __syncthreads();
    #pragma unroll
    for (int r = 0; r < 32; r += 8)
        g_rbt[(size_t)(l0 + ty + r) * CD + d0 + tx] = t[tx][ty + r];
}

__global__ void sampler_k(const float* __restrict__ x)
{
    int blk = blockIdx.x;
    int b = blk >> 13, l = blk & (CL - 1);
    int tid = threadIdx.x;
    int d4 = tid * 4;
    int g = tid >> 5;
    float off = g_offs[(size_t)(b * 4 + g) * CL + l];
    float vg = (float)l + off;
    float gg = 2.f * vg / 8195.f - 1.f;
    float ps = ((gg + 1.f) * 8192.f - 1.f) * 0.5f;
    float p0 = floorf(ps);
    float w1 = ps - p0;
    int i0 = (int)p0, i1 = i0 + 1;
    float4 a = make_float4(0.f, 0.f, 0.f, 0.f);
    float4 c = make_float4(0.f, 0.f, 0.f, 0.f);
    if (i0 >= 0 && i0 < CL) a = *(const float4*)(x + ((size_t)b * CL + i0) * CD + d4);
    if (i1 >= 0 && i1 < CL) c = *(const float4*)(x + ((size_t)b * CL + i1) * CD + d4);
    float w0 = 1.f - w1;
    float s0 = a.x*w0 + c.x*w1, s1 = a.y*w0 + c.y*w1;
    float s2 = a.z*w0 + c.z*w1, s3 = a.w*w0 + c.w*w1;
    size_t idx = ((size_t)b * CL + l) * CD + d4;
    splith(s0, s1, g_xsh + idx,     g_xsl + idx);
    splith(s2, s3, g_xsh + idx + 2, g_xsl + idx + 2);
}

__global__ void softmax_k()
{
    int bh = blockIdx.x, i = threadIdx.x;
    const float scale = 0.04419417382415922f;
    float v[64];
    for (int j = 0; j < 64; j++) {
        float s = 0.f;
        #pragma unroll
        for (int c = 0; c < 8; c++) s += g_part[((size_t)c * 32 + bh) * 4096 + i * 64 + j];
        v[j] = s * scale;
    }
    float mx = v[0];
    for (int j = 1; j < 64; j++) mx = fmaxf(mx, v[j]);
    float sum = 0.f;
    for (int j = 0; j < 64; j++) { v[j] = expf(v[j] - mx); sum += v[j]; }
    float inv = 1.f / sum;
    for (int j = 0; j < 64; j++) g_attn[(size_t)bh * 4096 + i * 64 + j] = v[j] * inv;
}

__global__ void weff_k(const float* __restrict__ Wout)
{
    __shared__ float As[64 * 64];
    int b = blockIdx.x, h = blockIdx.y, tid = threadIdx.x;
    for (int idx = tid; idx < 4096; idx += 256)
        As[idx] = g_attn[((size_t)(b * 8 + h)) * 4096 + idx];
    __syncthreads();
    for (int o = tid; o < CD; o += 256) {
        float wr[64];
        #pragma unroll
        for (int i = 0; i < 64; i++) wr[i] = Wout[(size_t)o * CD + h * 64 + i];
        for (int j = 0; j < 64; j++) {
            float s = 0.f;
            #pragma unroll
            for (int i = 0; i < 64; i++) s += wr[i] * As[i * 64 + j];
            g_wef[((size_t)b * CD + o) * CD + h * 64 + j] = __float2half_rn(s);
        }
    }
}

// ======================= launch =======================
extern "C" void kernel_launch(void* const* d_in, const int* in_sizes, int n_in,
                              void* d_out, int out_size)
{
    const float* x     = (const float*)d_in[0];
    const float* Wq    = (const float*)d_in[1];
    const float* bq    = (const float*)d_in[2];
    const float* Wk    = (const float*)d_in[3];
    const float* bk    = (const float*)d_in[4];
    const float* Wv    = (const float*)d_in[5];
    const float* bv    = (const float*)d_in[6];
    const float* Woff1 = (const float*)d_in[7];
    const float* boff1 = (const float*)d_in[8];
    const float* Woff2 = (const float*)d_in[9];
    const float* boff2 = (const float*)d_in[10];
    const float* relb  = (const float*)d_in[11];
    const float* Wout  = (const float*)d_in[12];
    const float* bout  = (const float*)d_in[13];
    float* out = (float*)d_out;

    cudaFuncSetAttribute(gemm_f16,   cudaFuncAttributeMaxDynamicSharedMemorySize, FSMEM);
    cudaFuncSetAttribute(gemm_h2,    cudaFuncAttributeMaxDynamicSharedMemorySize, HSMEM);
    cudaFuncSetAttribute(scores_f16, cudaFuncAttributeMaxDynamicSharedMemorySize, SSMEM);

    transpose_rb<<<dim3(CL/32, CD/32), dim3(32, 8)>>>(relb);
    cvt_f16<<<(CB*CL*CD/4 + 255)/256, 256>>>(x,  CB*CL*CD/4, 0);
    cvt_f16<<<(CD*CD/4 + 255)/256,    256>>>(Wq, CD*CD/4,    1);
    cvt_f16<<<(CD*CD/4 + 255)/256,    256>>>(Wk, CD*CD/4,    2);
    cvt_f16<<<(CD*CD/4 + 255)/256,    256>>>(Wv, CD*CD/4,    3);
    compose_off<<<1, 640>>>(Woff1, boff1, Woff2, boff2);

    gemm_f16<<<dim3(64, 4, CB), 256, FSMEM>>>(bq, 0);        // q -> fp16 chan-major
    offsets_fused<<<dim3(64, 16), 128>>>();                  // composed conv1+conv2+tanh
    sampler_k<<<CB*CL, 128>>>(x);                            // bilinear -> xs fp16 split
    gemm_f16<<<dim3(64, 4, CB), 256, FSMEM>>>(bk, 1);        // k -> fp16 chan-major
    gemm_h2<<<dim3(4, 64, CB), 256, HSMEM>>>(bv, nullptr, 0);// v (+relb) -> fp16 split
    scores_f16<<<dim3(32, 8), 256, SSMEM>>>();               // q·kᵀ split-K
    softmax_k<<<32, 64>>>();
    weff_k<<<dim3(CB, 8), 256>>>(Wout);                      // fold attn into Wout -> fp16
    gemm_h2<<<dim3(4, 64, CB), 256, HSMEM>>>(bout, out, 1);  // final -> fp32 out
}

// round 11
// speedup vs baseline: 4.3951x; 1.1472x over previous
#include <cuda_runtime.h>
#include <cuda_bf16.h>
#include <cuda_fp16.h>
#include <cstdint>

#define CL 8192
#define CD 512
#define CB 4

// ---------------- fp16 planes (all single-product now) ----------------
__device__ __half g_xf [CB*CL*CD];                 // x row-major
__device__ __half g_xsh[CB*CL*CD];                 // sampled x row-major
__device__ __half g_qf [CB*CD*CL];                 // q chan-major
__device__ __half g_kf [CB*CD*CL];                 // k chan-major
__device__ __half g_vh [CB*CL*CD];                 // v row-major
__device__ __half g_wqf[CD*CD], g_wkf[CD*CD], g_wvf[CD*CD];
__device__ __half g_wef[CB*CD*CD];                 // folded attn+Wout
// fp32 scratch
__device__ float g_offs[16*CL];
__device__ float g_rbt[CL*CD];
__device__ float g_part[8*32*64*64];
__device__ float g_attn[32*64*64];
__device__ float g_weff1[640];                     // composed offset conv kernel
__device__ float g_beff;                           // composed bias
__device__ float g_b2v;                            // raw b2 (lq<2 case)

// ======================= helpers =======================
__device__ __forceinline__ uint32_t smem_u32(const void* p){
    uint32_t a;
    asm("{ .reg .u64 t; cvta.to.shared.u64 t, %1; cvt.u32.u64 %0, t; }" : "=r"(a) : "l"(p));
    return a;
}
__device__ __forceinline__ void mma_f16(float* c, const uint32_t* a, const uint32_t* b){
    asm volatile("mma.sync.aligned.m16n8k16.row.col.f32.f16.f16.f32 "
        "{%0,%1,%2,%3}, {%4,%5,%6,%7}, {%8,%9}, {%0,%1,%2,%3};"
        : "+f"(c[0]), "+f"(c[1]), "+f"(c[2]), "+f"(c[3])
        : "r"(a[0]), "r"(a[1]), "r"(a[2]), "r"(a[3]), "r"(b[0]), "r"(b[1]));
}
__device__ __forceinline__ void ldsm4(uint32_t* r, uint32_t addr){
    asm volatile("ldmatrix.sync.aligned.m8n8.x4.shared.b16 {%0,%1,%2,%3}, [%4];"
        : "=r"(r[0]), "=r"(r[1]), "=r"(r[2]), "=r"(r[3]) : "r"(addr));
}
__device__ __forceinline__ void ldsm2(uint32_t* r, uint32_t addr){
    asm volatile("ldmatrix.sync.aligned.m8n8.x2.shared.b16 {%0,%1}, [%2];"
        : "=r"(r[0]), "=r"(r[1]) : "r"(addr));
}
__device__ __forceinline__ void cpa16(uint32_t dst, const void* src){
    asm volatile("cp.async.cg.shared.global [%0], [%1], 16;" :: "r"(dst), "l"(src));
}
#define CPA_COMMIT() asm volatile("cp.async.commit_group;" ::: "memory")
#define CPA_WAIT1()  asm volatile("cp.async.wait_group 1;" ::: "memory")
#define CPA_WAIT0()  asm volatile("cp.async.wait_group 0;" ::: "memory")

#define STRB 80                 // bytes per plane row (32 halves + pad)
#define PL   10240              // 128 rows * 80
#define BUF1 20480              // A,B
#define FSMEM (3*BUF1)          // 3-stage

// fill one plane via cp.async: ROWS x 32 halves
template<int ROWS, typename T>
__device__ __forceinline__ void fill_p(uint32_t sdst, const T* P,
    size_t row0, int ld, int kof, int tid)
{
    constexpr int IT = (ROWS*4)/256;
    #pragma unroll
    for (int i = 0; i < IT; i++) {
        int o = tid + i*256;
        int row = o >> 2, seg = o & 3;
        cpa16(sdst + row*STRB + seg*16, P + (row0 + row)*(size_t)ld + kof + seg*8);
    }
}

// fp16 single-product chunk (128x128 tile, warp 64x32)
__device__ __forceinline__ void mma_chunk1(float acc[4][4][4], uint32_t s0, int wm, int wn, int lane){
    #pragma unroll
    for (int ks = 0; ks < 2; ks++) {
        uint32_t af[4][4], bf[4][2];
        #pragma unroll
        for (int i = 0; i < 4; i++)
            ldsm4(af[i], s0 + (wm*64 + i*16 + (lane & 15))*STRB + ks*32 + (lane >> 4)*16);
        #pragma unroll
        for (int j = 0; j < 4; j++)
            ldsm2(bf[j], s0 + PL + (wn*32 + j*8 + (lane & 7))*STRB + ks*32 + ((lane >> 3) & 1)*16);
        #pragma unroll
        for (int i = 0; i < 4; i++)
            #pragma unroll
            for (int j = 0; j < 4; j++)
                mma_f16(acc[i][j], af[i], bf[j]);
    }
}

// ======================= prep kernels =======================
__global__ void cvt_f16(const float* __restrict__ src, int n4, int mode)
{
    __half* dst;
    switch (mode) {
        case 0:  dst = g_xf;  break;
        case 1:  dst = g_wqf; break;
        case 2:  dst = g_wkf; break;
        default: dst = g_wvf; break;
    }
    int i = blockIdx.x*256 + threadIdx.x;
    if (i >= n4) return;
    float4 v = ((const float4*)src)[i];
    __half2 a = __floats2half2_rn(v.x, v.y);
    __half2 b = __floats2half2_rn(v.z, v.w);
    *(uint2*)(dst + i*4) = make_uint2(*(uint32_t*)&a, *(uint32_t*)&b);
}

// compose conv2(conv1(.)): Weff[ci][t] = sum_co w2[co]*W1[co][ci][t]; beff = b2 + sum w2*b1
__global__ void compose_off(const float* __restrict__ W1, const float* __restrict__ b1,
                            const float* __restrict__ w2, const float* __restrict__ b2)
{
    int tid = threadIdx.x;
    if (tid < 640) {
        float s = 0.f;
        #pragma unroll 4
        for (int co = 0; co < 128; co++) s += w2[co] * W1[co*640 + tid];
        g_weff1[tid] = s;
    }
    if (tid == 0) {
        float b = b2[0];
        for (int co = 0; co < 128; co++) b += w2[co] * b1[co];
        g_beff = b;
        g_b2v = b2[0];
    }
}

// ======================= unified fp16 GEMM — 3-stage pipeline =======================
// mode 0: q  = Wq·x    -> g_qf  chan-major (grid x=Ltile64, y=Dtile4, z=b)
// mode 1: k  = Wk·xs   -> g_kf  chan-major (same grid)
// mode 2: v  = xs·Wvᵀ (+bv+relb) -> g_vh row-major fp16 (grid x=Dtile4, y=Ltile64, z=b)
// mode 3: out= v·Weffᵀ (+bout)   -> fp32 Out            (same grid)
__global__ __launch_bounds__(256, 2)
void gemm_f16(const float* __restrict__ bias, float* __restrict__ Out, int mode)
{
    extern __shared__ __align__(16) char smem[];
    uint32_t sb = smem_u32(smem);
    int tid = threadIdx.x, lane = tid & 31, wid = tid >> 5;
    int wm = wid >> 2, wn = wid & 3;
    int bx = blockIdx.x, by = blockIdx.y, bz = blockIdx.z;

    const __half *A, *B;
    size_t arow0, brow0;
    if (mode == 0)      { A = g_wqf; arow0 = (size_t)by*128; B = g_xf;  brow0 = (size_t)bz*CL + bx*128; }
    else if (mode == 1) { A = g_wkf; arow0 = (size_t)by*128; B = g_xsh; brow0 = (size_t)bz*CL + bx*128; }
    else if (mode == 2) { A = g_xsh; arow0 = (size_t)bz*CL + by*128; B = g_wvf; brow0 = (size_t)bx*128; }
    else                { A = g_vh;  arow0 = (size_t)bz*CL + by*128; B = g_wef; brow0 = (size_t)bz*CD + bx*128; }

    float acc[4][4][4] = {};

    fill_p<128>(sb,              A, arow0, CD, 0,  tid);
    fill_p<128>(sb + PL,         B, brow0, CD, 0,  tid);
    CPA_COMMIT();
    fill_p<128>(sb + BUF1,       A, arow0, CD, 32, tid);
    fill_p<128>(sb + BUF1 + PL,  B, brow0, CD, 32, tid);
    CPA_COMMIT();

    for (int ch = 0; ch < 16; ch++) {
        if (ch + 1 < 16) CPA_WAIT1(); else CPA_WAIT0();
        __syncthreads();
        if (ch + 2 < 16) {
            uint32_t nx = sb + ((ch+2) % 3)*BUF1;
            fill_p<128>(nx,      A, arow0, CD, (ch+2)*32, tid);
            fill_p<128>(nx + PL, B, brow0, CD, (ch+2)*32, tid);
            CPA_COMMIT();
        }
        mma_chunk1(acc, sb + (ch % 3)*BUF1, wm, wn, lane);
    }

    int qr = lane >> 2, qc = (lane & 3)*2;
    if (mode <= 1) {
        __half* Cp = mode ? g_kf : g_qf;
        #pragma unroll
        for (int i = 0; i < 4; i++)
            #pragma unroll
            for (int half = 0; half < 2; half++) {
                int m = by*128 + wm*64 + i*16 + qr + half*8;
                float bm = bias[m];
                size_t rowo = ((size_t)bz*CD + m)*CL + bx*128 + wn*32 + qc;
                #pragma unroll
                for (int j = 0; j < 4; j++) {
                    __half2 h = __floats2half2_rn(acc[i][j][half*2+0] + bm,
                                                  acc[i][j][half*2+1] + bm);
                    *(__half2*)(Cp + rowo + j*8) = h;
                }
            }
    } else if (mode == 2) {
        #pragma unroll
        for (int i = 0; i < 4; i++)
            #pragma unroll
            for (int half = 0; half < 2; half++) {
                int lrow = by*128 + wm*64 + i*16 + qr + half*8;
                size_t rowo = ((size_t)bz*CL + lrow)*CD + bx*128 + wn*32 + qc;
                const float* bn = bias + bx*128 + wn*32 + qc;
                const float* rp = g_rbt + (size_t)lrow*CD + bx*128 + wn*32 + qc;
                #pragma unroll
                for (int j = 0; j < 4; j++) {
                    __half2 h = __floats2half2_rn(acc[i][j][half*2+0] + bn[j*8+0] + rp[j*8+0],
                                                  acc[i][j][half*2+1] + bn[j*8+1] + rp[j*8+1]);
                    *(__half2*)(g_vh + rowo + j*8) = h;
                }
            }
    } else {
        #pragma unroll
        for (int i = 0; i < 4; i++)
            #pragma unroll
            for (int half = 0; half < 2; half++) {
                int lrow = by*128 + wm*64 + i*16 + qr + half*8;
                float* dst = Out + ((size_t)bz*CL + lrow)*CD + bx*128 + wn*32 + qc;
                const float* bn = bias + bx*128 + wn*32 + qc;
                #pragma unroll
                for (int j = 0; j < 4; j++) {
                    float2 v;
                    v.x = acc[i][j][half*2+0] + bn[j*8+0];
                    v.y = acc[i][j][half*2+1] + bn[j*8+1];
                    *(float2*)(dst + j*8) = v;
                }
            }
    }
}

// ======================= fused offsets (composed conv1+conv2 + tanh) =======================
__global__ void offsets_fused()
{
    __shared__ __half tile[128*132];
    __shared__ float wsh[640];
    int tid = threadIdx.x;           // 128
    int bg = blockIdx.y;
    int l0 = blockIdx.x * 128;

    for (int i = tid; i < 640; i += 128) wsh[i] = g_weff1[i];
    for (int idx = tid; idx < 128*132; idx += 128) {
        int cj = idx / 132, j = idx - cj*132;
        int l = l0 - 4 + j;
        tile[idx] = (l >= 0) ? g_qf[((size_t)(bg*128 + cj))*CL + l] : __float2half(0.f);
    }
    __syncthreads();

    int lq = l0 + tid;
    float sum;
    if (lq >= 2) {
        sum = g_beff;
        #pragma unroll 4
        for (int cj = 0; cj < 128; cj++) {
            const __half* tr = tile + cj*132 + tid;
            const float* wr = wsh + cj*5;
            #pragma unroll
            for (int t = 0; t < 5; t++)
                sum += wr[t] * __half2float(tr[t]);
        }
    } else {
        sum = g_b2v;
    }
    g_offs[(size_t)bg * CL + lq] = 5.f * tanhf(sum);
}

// ======================= scores (fp16 single) — 3-stage pipeline =======================
#define PS    5120
#define SBUF1 10240
#define SSMEM (3*SBUF1)
__global__ __launch_bounds__(256)
void scores_f16()
{
    extern __shared__ __align__(16) char smem[];
    uint32_t sb = smem_u32(smem);
    int tid = threadIdx.x, lane = tid & 31, wid = tid >> 5;
    int wm = wid >> 2, wn = wid & 3;
    int bh = blockIdx.x, chunk = blockIdx.y;
    size_t chbase = (size_t)(bh >> 3)*CD + (size_t)(bh & 7)*64;
    int kof0 = chunk*1024;

    float acc[2][2][4] = {};

    fill_p<64>(sb,              g_qf, chbase, CL, kof0,      tid);
    fill_p<64>(sb + PS,         g_kf, chbase, CL, kof0,      tid);
    CPA_COMMIT();
    fill_p<64>(sb + SBUF1,      g_qf, chbase, CL, kof0 + 32, tid);
    fill_p<64>(sb + SBUF1 + PS, g_kf, chbase, CL, kof0 + 32, tid);
    CPA_COMMIT();

    for (int ch = 0; ch < 32; ch++) {
        if (ch + 1 < 32) CPA_WAIT1(); else CPA_WAIT0();
        __syncthreads();
        if (ch + 2 < 32) {
            uint32_t nx = sb + ((ch+2) % 3)*SBUF1;
            fill_p<64>(nx,      g_qf, chbase, CL, kof0 + (ch+2)*32, tid);
            fill_p<64>(nx + PS, g_kf, chbase, CL, kof0 + (ch+2)*32, tid);
            CPA_COMMIT();
        }
        uint32_t s0 = sb + (ch % 3)*SBUF1;
        #pragma unroll
        for (int ks = 0; ks < 2; ks++) {
            uint32_t af[2][4], bf[2][2];
            #pragma unroll
            for (int i = 0; i < 2; i++)
                ldsm4(af[i], s0 + (wm*32 + i*16 + (lane & 15))*STRB + ks*32 + (lane >> 4)*16);
            #pragma unroll
            for (int j = 0; j < 2; j++)
                ldsm2(bf[j], s0 + PS + (wn*16 + j*8 + (lane & 7))*STRB + ks*32 + ((lane >> 3) & 1)*16);
            #pragma unroll
            for (int i = 0; i < 2; i++)
                #pragma unroll
                for (int j = 0; j < 2; j++)
                    mma_f16(acc[i][j], af[i], bf[j]);
        }
    }

    int qr = lane >> 2, qc = (lane & 3)*2;
    float* base = g_part + ((size_t)chunk*32 + bh)*4096;
    #pragma unroll
    for (int i = 0; i < 2; i++)
        #pragma unroll
        for (int half = 0; half < 2; half++) {
            int m = wm*32 + i*16 + qr + half*8;
            float* dst = base + (size_t)m*64 + wn*16 + qc;
            #pragma unroll
            for (int j = 0; j < 2; j++) {
                float2 v;
                v.x = acc[i][j][half*2+0];
                v.y = acc[i][j][half*2+1];
                *(float2*)(dst + j*8) = v;
            }
        }
}

// ======================= small kernels =======================
__global__ void transpose_rb(const float* __restrict__ rb)
{
    __shared__ float t[32][33];
    int l0 = blockIdx.x * 32, d0 = blockIdx.y * 32;
    int tx = threadIdx.x, ty = threadIdx.y;
    #pragma unroll
    for (int r = 0; r < 32; r += 8)
        t[ty + r][tx] = rb[(size_t)(d0 + ty + r) * CL + l0 + tx];
    __syncthreads();
    #pragma unroll
    for (int r = 0; r < 32; r += 8)
        g_rbt[(size_t)(l0 + ty + r) * CD + d0 + tx] = t[tx][ty + r];
}

__global__ void sampler_k(const float* __restrict__ x)
{
    int blk = blockIdx.x;
    int b = blk >> 13, l = blk & (CL - 1);
    int tid = threadIdx.x;
    int d4 = tid * 4;
    int g = tid >> 5;
    float off = g_offs[(size_t)(b * 4 + g) * CL + l];
    float vg = (float)l + off;
    float gg = 2.f * vg / 8195.f - 1.f;
    float ps = ((gg + 1.f) * 8192.f - 1.f) * 0.5f;
    float p0 = floorf(ps);
    float w1 = ps - p0;
    int i0 = (int)p0, i1 = i0 + 1;
    float4 a = make_float4(0.f, 0.f, 0.f, 0.f);
    float4 c = make_float4(0.f, 0.f, 0.f, 0.f);
    if (i0 >= 0 && i0 < CL) a = *(const float4*)(x + ((size_t)b * CL + i0) * CD + d4);
    if (i1 >= 0 && i1 < CL) c = *(const float4*)(x + ((size_t)b * CL + i1) * CD + d4);
    float w0 = 1.f - w1;
    __half2 h0 = __floats2half2_rn(a.x*w0 + c.x*w1, a.y*w0 + c.y*w1);
    __half2 h1 = __floats2half2_rn(a.z*w0 + c.z*w1, a.w*w0 + c.w*w1);
    size_t idx = ((size_t)b * CL + l) * CD + d4;
    *(uint2*)(g_xsh + idx) = make_uint2(*(uint32_t*)&h0, *(uint32_t*)&h1);
}

__global__ void softmax_k()
{
    int bh = blockIdx.x, i = threadIdx.x;
    const float scale = 0.04419417382415922f;
    float v[64];
    for (int j = 0; j < 64; j++) {
        float s = 0.f;
        #pragma unroll
        for (int c = 0; c < 8; c++) s += g_part[((size_t)c * 32 + bh) * 4096 + i * 64 + j];
        v[j] = s * scale;
    }
    float mx = v[0];
    for (int j = 1; j < 64; j++) mx = fmaxf(mx, v[j]);
    float sum = 0.f;
    for (int j = 0; j < 64; j++) { v[j] = expf(v[j] - mx); sum += v[j]; }
    float inv = 1.f / sum;
    for (int j = 0; j < 64; j++) g_attn[(size_t)bh * 4096 + i * 64 + j] = v[j] * inv;
}

__global__ void weff_k(const float* __restrict__ Wout)
{
    __shared__ float As[64 * 64];
    int b = blockIdx.x, h = blockIdx.y, tid = threadIdx.x;
    for (int idx = tid; idx < 4096; idx += 256)
        As[idx] = g_attn[((size_t)(b * 8 + h)) * 4096 + idx];
    __syncthreads();
    for (int o = tid; o < CD; o += 256) {
        float wr[64];
        #pragma unroll
        for (int i = 0; i < 64; i++) wr[i] = Wout[(size_t)o * CD + h * 64 + i];
        for (int j = 0; j < 64; j++) {
            float s = 0.f;
            #pragma unroll
            for (int i = 0; i < 64; i++) s += wr[i] * As[i * 64 + j];
            g_wef[((size_t)b * CD + o) * CD + h * 64 + j] = __float2half_rn(s);
        }
    }
}

// ======================= launch =======================
extern "C" void kernel_launch(void* const* d_in, const int* in_sizes, int n_in,
                              void* d_out, int out_size)
{
    const float* x     = (const float*)d_in[0];
    const float* Wq    = (const float*)d_in[1];
    const float* bq    = (const float*)d_in[2];
    const float* Wk    = (const float*)d_in[3];
    const float* bk    = (const float*)d_in[4];
    const float* Wv    = (const float*)d_in[5];
    const float* bv    = (const float*)d_in[6];
    const float* Woff1 = (const float*)d_in[7];
    const float* boff1 = (const float*)d_in[8];
    const float* Woff2 = (const float*)d_in[9];
    const float* boff2 = (const float*)d_in[10];
    const float* relb  = (const float*)d_in[11];
    const float* Wout  = (const float*)d_in[12];
    const float* bout  = (const float*)d_in[13];
    float* out = (float*)d_out;

    cudaFuncSetAttribute(gemm_f16,   cudaFuncAttributeMaxDynamicSharedMemorySize, FSMEM);
    cudaFuncSetAttribute(scores_f16, cudaFuncAttributeMaxDynamicSharedMemorySize, SSMEM);

    transpose_rb<<<dim3(CL/32, CD/32), dim3(32, 8)>>>(relb);
    cvt_f16<<<(CB*CL*CD/4 + 255)/256, 256>>>(x,  CB*CL*CD/4, 0);
    cvt_f16<<<(CD*CD/4 + 255)/256,    256>>>(Wq, CD*CD/4,    1);
    cvt_f16<<<(CD*CD/4 + 255)/256,    256>>>(Wk, CD*CD/4,    2);
    cvt_f16<<<(CD*CD/4 + 255)/256,    256>>>(Wv, CD*CD/4,    3);
    compose_off<<<1, 640>>>(Woff1, boff1, Woff2, boff2);

    gemm_f16<<<dim3(64, 4, CB), 256, FSMEM>>>(bq, nullptr, 0);   // q -> fp16 chan-major
    offsets_fused<<<dim3(64, 16), 128>>>();                      // composed conv1+conv2+tanh
    sampler_k<<<CB*CL, 128>>>(x);                                // bilinear -> xs fp16
    gemm_f16<<<dim3(64, 4, CB), 256, FSMEM>>>(bk, nullptr, 1);   // k -> fp16 chan-major
    gemm_f16<<<dim3(4, 64, CB), 256, FSMEM>>>(bv, nullptr, 2);   // v (+relb) -> fp16
    scores_f16<<<dim3(32, 8), 256, SSMEM>>>();                   // q·kᵀ split-K
    softmax_k<<<32, 64>>>();
    weff_k<<<dim3(CB, 8), 256>>>(Wout);                          // fold attn into Wout -> fp16
    gemm_f16<<<dim3(4, 64, CB), 256, FSMEM>>>(bout, out, 3);     // final -> fp32 out
}

// round 12
// speedup vs baseline: 4.6250x; 1.0523x over previous
#include <cuda_runtime.h>
#include <cuda_bf16.h>
#include <cuda_fp16.h>
#include <cstdint>

#define CL 8192
#define CD 512
#define CB 4

// ---------------- fp16 planes ----------------
__device__ __half g_xf [CB*CL*CD];                 // x row-major
__device__ __half g_xsh[CB*CL*CD];                 // sampled x row-major
__device__ __half g_qf [CB*CD*CL];                 // q chan-major
__device__ __half g_kf [CB*CD*CL];                 // k chan-major
__device__ __half g_vh [CB*CL*CD];                 // v row-major
__device__ __half g_wqf[CD*CD], g_wkf[CD*CD], g_wvf[CD*CD];
__device__ __half g_wef[CB*CD*CD];                 // folded attn+Wout
// fp32 scratch
__device__ float g_offs[16*CL];
__device__ float g_rbt[CL*CD];
__device__ float g_part[8*32*64*64];
__device__ float g_attn[32*64*64];
__device__ float g_weff1[640];                     // composed offset conv kernel
__device__ float g_beff;                           // composed bias
__device__ float g_b2v;                            // raw b2 (lq<2 case)

// ======================= helpers =======================
__device__ __forceinline__ uint32_t smem_u32(const void* p){
    uint32_t a;
    asm("{ .reg .u64 t; cvta.to.shared.u64 t, %1; cvt.u32.u64 %0, t; }" : "=r"(a) : "l"(p));
    return a;
}
__device__ __forceinline__ void mma_f16(float* c, const uint32_t* a, const uint32_t* b){
    asm volatile("mma.sync.aligned.m16n8k16.row.col.f32.f16.f16.f32 "
        "{%0,%1,%2,%3}, {%4,%5,%6,%7}, {%8,%9}, {%0,%1,%2,%3};"
        : "+f"(c[0]), "+f"(c[1]), "+f"(c[2]), "+f"(c[3])
        : "r"(a[0]), "r"(a[1]), "r"(a[2]), "r"(a[3]), "r"(b[0]), "r"(b[1]));
}
__device__ __forceinline__ void ldsm4(uint32_t* r, uint32_t addr){
    asm volatile("ldmatrix.sync.aligned.m8n8.x4.shared.b16 {%0,%1,%2,%3}, [%4];"
        : "=r"(r[0]), "=r"(r[1]), "=r"(r[2]), "=r"(r[3]) : "r"(addr));
}
__device__ __forceinline__ void ldsm2(uint32_t* r, uint32_t addr){
    asm volatile("ldmatrix.sync.aligned.m8n8.x2.shared.b16 {%0,%1}, [%2];"
        : "=r"(r[0]), "=r"(r[1]) : "r"(addr));
}
__device__ __forceinline__ void cpa16(uint32_t dst, const void* src){
    asm volatile("cp.async.cg.shared.global [%0], [%1], 16;" :: "r"(dst), "l"(src));
}
#define CPA_COMMIT() asm volatile("cp.async.commit_group;" ::: "memory")
#define CPA_WAIT1()  asm volatile("cp.async.wait_group 1;" ::: "memory")
#define CPA_WAIT0()  asm volatile("cp.async.wait_group 0;" ::: "memory")

// Kc = 64 halves per chunk row
#define STRB 144                // bytes per plane row (64 halves = 128B + 16B pad)
#define PL   18432              // 128 rows * 144
#define BUF1 36864              // A,B planes
#define FSMEM (3*BUF1)          // 110592; 2 CTAs = 221184 <= 228KB
#define PS    9216              // 64 rows * 144
#define SBUF1 18432
#define SSMEM (3*SBUF1)

// fill one plane via cp.async: ROWS x 64 halves (128B per row in 8 segs)
template<int ROWS, typename T>
__device__ __forceinline__ void fill_p(uint32_t sdst, const T* P,
    size_t row0, int ld, int kof, int tid)
{
    constexpr int IT = (ROWS*8)/256;
    #pragma unroll
    for (int i = 0; i < IT; i++) {
        int o = tid + i*256;
        int row = o >> 3, seg = o & 7;
        cpa16(sdst + row*STRB + seg*16, P + (row0 + row)*(size_t)ld + kof + seg*8);
    }
}

// fp16 chunk consumer, Kc=64 (128x128 tile, warp 64x32)
__device__ __forceinline__ void mma_chunk1(float acc[4][4][4], uint32_t s0, int wm, int wn, int lane){
    #pragma unroll
    for (int ks = 0; ks < 4; ks++) {
        uint32_t af[4][4], bf[4][2];
        #pragma unroll
        for (int i = 0; i < 4; i++)
            ldsm4(af[i], s0 + (wm*64 + i*16 + (lane & 15))*STRB + ks*32 + (lane >> 4)*16);
        #pragma unroll
        for (int j = 0; j < 4; j++)
            ldsm2(bf[j], s0 + PL + (wn*32 + j*8 + (lane & 7))*STRB + ks*32 + ((lane >> 3) & 1)*16);
        #pragma unroll
        for (int i = 0; i < 4; i++)
            #pragma unroll
            for (int j = 0; j < 4; j++)
                mma_f16(acc[i][j], af[i], bf[j]);
    }
}

// ======================= prep kernels =======================
__global__ void cvt_f16(const float* __restrict__ src, int n4, int mode)
{
    __half* dst;
    switch (mode) {
        case 0:  dst = g_xf;  break;
        case 1:  dst = g_wqf; break;
        case 2:  dst = g_wkf; break;
        default: dst = g_wvf; break;
    }
    int i = blockIdx.x*256 + threadIdx.x;
    if (i >= n4) return;
    float4 v = ((const float4*)src)[i];
    __half2 a = __floats2half2_rn(v.x, v.y);
    __half2 b = __floats2half2_rn(v.z, v.w);
    *(uint2*)(dst + i*4) = make_uint2(*(uint32_t*)&a, *(uint32_t*)&b);
}

// compose conv2(conv1(.)): Weff[ci][t] = sum_co w2[co]*W1[co][ci][t]; beff = b2 + sum w2*b1
__global__ void compose_off(const float* __restrict__ W1, const float* __restrict__ b1,
                            const float* __restrict__ w2, const float* __restrict__ b2)
{
    int tid = threadIdx.x;
    if (tid < 640) {
        float s = 0.f;
        #pragma unroll 4
        for (int co = 0; co < 128; co++) s += w2[co] * W1[co*640 + tid];
        g_weff1[tid] = s;
    }
    if (tid == 0) {
        float b = b2[0];
        for (int co = 0; co < 128; co++) b += w2[co] * b1[co];
        g_beff = b;
        g_b2v = b2[0];
    }
}

// ======================= unified fp16 GEMM — 3-stage pipeline, Kc=64 =======================
// mode 0: q  = Wq·x    -> g_qf  chan-major (grid x=Ltile64, y=Dtile4, z=b)
// mode 1: k  = Wk·xs   -> g_kf  chan-major (same grid)
// mode 2: v  = xs·Wvᵀ (+bv+relb) -> g_vh row-major fp16 (grid x=Dtile4, y=Ltile64, z=b)
// mode 3: out= v·Weffᵀ (+bout)   -> fp32 Out            (same grid)
__global__ __launch_bounds__(256, 2)
void gemm_f16(const float* __restrict__ bias, float* __restrict__ Out, int mode)
{
    extern __shared__ __align__(16) char smem[];
    uint32_t sb = smem_u32(smem);
    int tid = threadIdx.x, lane = tid & 31, wid = tid >> 5;
    int wm = wid >> 2, wn = wid & 3;
    int bx = blockIdx.x, by = blockIdx.y, bz = blockIdx.z;

    const __half *A, *B;
    size_t arow0, brow0;
    if (mode == 0)      { A = g_wqf; arow0 = (size_t)by*128; B = g_xf;  brow0 = (size_t)bz*CL + bx*128; }
    else if (mode == 1) { A = g_wkf; arow0 = (size_t)by*128; B = g_xsh; brow0 = (size_t)bz*CL + bx*128; }
    else if (mode == 2) { A = g_xsh; arow0 = (size_t)bz*CL + by*128; B = g_wvf; brow0 = (size_t)bx*128; }
    else                { A = g_vh;  arow0 = (size_t)bz*CL + by*128; B = g_wef; brow0 = (size_t)bz*CD + bx*128; }

    float acc[4][4][4] = {};

    fill_p<128>(sb,              A, arow0, CD, 0,  tid);
    fill_p<128>(sb + PL,         B, brow0, CD, 0,  tid);
    CPA_COMMIT();
    fill_p<128>(sb + BUF1,       A, arow0, CD, 64, tid);
    fill_p<128>(sb + BUF1 + PL,  B, brow0, CD, 64, tid);
    CPA_COMMIT();

    for (int ch = 0; ch < 8; ch++) {
        if (ch + 1 < 8) CPA_WAIT1(); else CPA_WAIT0();
        __syncthreads();
        if (ch + 2 < 8) {
            uint32_t nx = sb + ((ch+2) % 3)*BUF1;
            fill_p<128>(nx,      A, arow0, CD, (ch+2)*64, tid);
            fill_p<128>(nx + PL, B, brow0, CD, (ch+2)*64, tid);
            CPA_COMMIT();
        }
        mma_chunk1(acc, sb + (ch % 3)*BUF1, wm, wn, lane);
    }

    int qr = lane >> 2, qc = (lane & 3)*2;
    if (mode <= 1) {
        __half* Cp = mode ? g_kf : g_qf;
        #pragma unroll
        for (int i = 0; i < 4; i++)
            #pragma unroll
            for (int half = 0; half < 2; half++) {
                int m = by*128 + wm*64 + i*16 + qr + half*8;
                float bm = bias[m];
                size_t rowo = ((size_t)bz*CD + m)*CL + bx*128 + wn*32 + qc;
                #pragma unroll
                for (int j = 0; j < 4; j++) {
                    __half2 h = __floats2half2_rn(acc[i][j][half*2+0] + bm,
                                                  acc[i][j][half*2+1] + bm);
                    *(__half2*)(Cp + rowo + j*8) = h;
                }
            }
    } else if (mode == 2) {
        #pragma unroll
        for (int i = 0; i < 4; i++)
            #pragma unroll
            for (int half = 0; half < 2; half++) {
                int lrow = by*128 + wm*64 + i*16 + qr + half*8;
                size_t rowo = ((size_t)bz*CL + lrow)*CD + bx*128 + wn*32 + qc;
                const float* bn = bias + bx*128 + wn*32 + qc;
                const float* rp = g_rbt + (size_t)lrow*CD + bx*128 + wn*32 + qc;
                #pragma unroll
                for (int j = 0; j < 4; j++) {
                    __half2 h = __floats2half2_rn(acc[i][j][half*2+0] + bn[j*8+0] + rp[j*8+0],
                                                  acc[i][j][half*2+1] + bn[j*8+1] + rp[j*8+1]);
                    *(__half2*)(g_vh + rowo + j*8) = h;
                }
            }
    } else {
        #pragma unroll
        for (int i = 0; i < 4; i++)
            #pragma unroll
            for (int half = 0; half < 2; half++) {
                int lrow = by*128 + wm*64 + i*16 + qr + half*8;
                float* dst = Out + ((size_t)bz*CL + lrow)*CD + bx*128 + wn*32 + qc;
                const float* bn = bias + bx*128 + wn*32 + qc;
                #pragma unroll
                for (int j = 0; j < 4; j++) {
                    float2 v;
                    v.x = acc[i][j][half*2+0] + bn[j*8+0];
                    v.y = acc[i][j][half*2+1] + bn[j*8+1];
                    *(float2*)(dst + j*8) = v;
                }
            }
    }
}

// ======================= fused offsets (composed conv1+conv2 + tanh) =======================
__global__ void offsets_fused()
{
    __shared__ __half tile[128*132];
    __shared__ float wsh[640];
    int tid = threadIdx.x;           // 128
    int bg = blockIdx.y;
    int l0 = blockIdx.x * 128;

    for (int i = tid; i < 640; i += 128) wsh[i] = g_weff1[i];
    for (int idx = tid; idx < 128*132; idx += 128) {
        int cj = idx / 132, j = idx - cj*132;
        int l = l0 - 4 + j;
        tile[idx] = (l >= 0) ? g_qf[((size_t)(bg*128 + cj))*CL + l] : __float2half(0.f);
    }
    __syncthreads();

    int lq = l0 + tid;
    float sum;
    if (lq >= 2) {
        sum = g_beff;
        #pragma unroll 4
        for (int cj = 0; cj < 128; cj++) {
            const __half* tr = tile + cj*132 + tid;
            const float* wr = wsh + cj*5;
            #pragma unroll
            for (int t = 0; t < 5; t++)
                sum += wr[t] * __half2float(tr[t]);
        }
    } else {
        sum = g_b2v;
    }
    g_offs[(size_t)bg * CL + lq] = 5.f * tanhf(sum);
}

// ======================= scores (fp16) — 3-stage pipeline, Kc=64 =======================
__global__ __launch_bounds__(256)
void scores_f16()
{
    extern __shared__ __align__(16) char smem[];
    uint32_t sb = smem_u32(smem);
    int tid = threadIdx.x, lane = tid & 31, wid = tid >> 5;
    int wm = wid >> 2, wn = wid & 3;
    int bh = blockIdx.x, chunk = blockIdx.y;
    size_t chbase = (size_t)(bh >> 3)*CD + (size_t)(bh & 7)*64;
    int kof0 = chunk*1024;

    float acc[2][2][4] = {};

    fill_p<64>(sb,              g_qf, chbase, CL, kof0,      tid);
    fill_p<64>(sb + PS,         g_kf, chbase, CL, kof0,      tid);
    CPA_COMMIT();
    fill_p<64>(sb + SBUF1,      g_qf, chbase, CL, kof0 + 64, tid);
    fill_p<64>(sb + SBUF1 + PS, g_kf, chbase, CL, kof0 + 64, tid);
    CPA_COMMIT();

    for (int ch = 0; ch < 16; ch++) {
        if (ch + 1 < 16) CPA_WAIT1(); else CPA_WAIT0();
        __syncthreads();
        if (ch + 2 < 16) {
            uint32_t nx = sb + ((ch+2) % 3)*SBUF1;
            fill_p<64>(nx,      g_qf, chbase, CL, kof0 + (ch+2)*64, tid);
            fill_p<64>(nx + PS, g_kf, chbase, CL, kof0 + (ch+2)*64, tid);
            CPA_COMMIT();
        }
        uint32_t s0 = sb + (ch % 3)*SBUF1;
        #pragma unroll
        for (int ks = 0; ks < 4; ks++) {
            uint32_t af[2][4], bf[2][2];
            #pragma unroll
            for (int i = 0; i < 2; i++)
                ldsm4(af[i], s0 + (wm*32 + i*16 + (lane & 15))*STRB + ks*32 + (lane >> 4)*16);
            #pragma unroll
            for (int j = 0; j < 2; j++)
                ldsm2(bf[j], s0 + PS + (wn*16 + j*8 + (lane & 7))*STRB + ks*32 + ((lane >> 3) & 1)*16);
            #pragma unroll
            for (int i = 0; i < 2; i++)
                #pragma unroll
                for (int j = 0; j < 2; j++)
                    mma_f16(acc[i][j], af[i], bf[j]);
        }
    }

    int qr = lane >> 2, qc = (lane & 3)*2;
    float* base = g_part + ((size_t)chunk*32 + bh)*4096;
    #pragma unroll
    for (int i = 0; i < 2; i++)
        #pragma unroll
        for (int half = 0; half < 2; half++) {
            int m = wm*32 + i*16 + qr + half*8;
            float* dst = base + (size_t)m*64 + wn*16 + qc;
            #pragma unroll
            for (int j = 0; j < 2; j++) {
                float2 v;
                v.x = acc[i][j][half*2+0];
                v.y = acc[i][j][half*2+1];
                *(float2*)(dst + j*8) = v;
            }
        }
}

// ======================= small kernels =======================
__global__ void transpose_rb(const float* __restrict__ rb)
{
    __shared__ float t[32][33];
    int l0 = blockIdx.x * 32, d0 = blockIdx.y * 32;
    int tx = threadIdx.x, ty = threadIdx.y;
    #pragma unroll
    for (int r = 0; r < 32; r += 8)
        t[ty + r][tx] = rb[(size_t)(d0 + ty + r) * CL + l0 + tx];
    __syncthreads();
    #pragma unroll
    for (int r = 0; r < 32; r += 8)
        g_rbt[(size_t)(l0 + ty + r) * CD + d0 + tx] = t[tx][ty + r];
}

__global__ void sampler_k(const float* __restrict__ x)
{
    int t = threadIdx.x;                   // 512: 4 positions x 128 channel-threads
    int li = blockIdx.x * 4 + (t >> 7);    // global b*CL + l index
    int b = li >> 13, l = li & (CL - 1);
    int tid = t & 127;
    int d4 = tid * 4;
    int g = tid >> 5;
    float off = g_offs[(size_t)(b * 4 + g) * CL + l];
    float vg = (float)l + off;
    float gg = 2.f * vg / 8195.f - 1.f;
    float ps = ((gg + 1.f) * 8192.f - 1.f) * 0.5f;
    float p0 = floorf(ps);
    float w1 = ps - p0;
    int i0 = (int)p0, i1 = i0 + 1;
    float4 a = make_float4(0.f, 0.f, 0.f, 0.f);
    float4 c = make_float4(0.f, 0.f, 0.f, 0.f);
    if (i0 >= 0 && i0 < CL) a = *(const float4*)(x + ((size_t)b * CL + i0) * CD + d4);
    if (i1 >= 0 && i1 < CL) c = *(const float4*)(x + ((size_t)b * CL + i1) * CD + d4);
    float w0 = 1.f - w1;
    __half2 h0 = __floats2half2_rn(a.x*w0 + c.x*w1, a.y*w0 + c.y*w1);
    __half2 h1 = __floats2half2_rn(a.z*w0 + c.z*w1, a.w*w0 + c.w*w1);
    size_t idx = ((size_t)b * CL + l) * CD + d4;
    *(uint2*)(g_xsh + idx) = make_uint2(*(uint32_t*)&h0, *(uint32_t*)&h1);
}

__global__ void softmax_k()
{
    int bh = blockIdx.x, i = threadIdx.x;
    const float scale = 0.04419417382415922f;
    float v[64];
    for (int j = 0; j < 64; j++) {
        float s = 0.f;
        #pragma unroll
        for (int c = 0; c < 8; c++) s += g_part[((size_t)c * 32 + bh) * 4096 + i * 64 + j];
        v[j] = s * scale;
    }
    float mx = v[0];
    for (int j = 1; j < 64; j++) mx = fmaxf(mx, v[j]);
    float sum = 0.f;
    for (int j = 0; j < 64; j++) { v[j] = expf(v[j] - mx); sum += v[j]; }
    float inv = 1.f / sum;
    for (int j = 0; j < 64; j++) g_attn[(size_t)bh * 4096 + i * 64 + j] = v[j] * inv;
}

__global__ void weff_k(const float* __restrict__ Wout)
{
    __shared__ float As[64 * 64];
    int b = blockIdx.x, h = blockIdx.y, tid = threadIdx.x;
    for (int idx = tid; idx < 4096; idx += 256)
        As[idx] = g_attn[((size_t)(b * 8 + h)) * 4096 + idx];
    __syncthreads();
    for (int o = tid; o < CD; o += 256) {
        float wr[64];
        #pragma unroll
        for (int i = 0; i < 64; i++) wr[i] = Wout[(size_t)o * CD + h * 64 + i];
        for (int j = 0; j < 64; j++) {
            float s = 0.f;
            #pragma unroll
            for (int i = 0; i < 64; i++) s += wr[i] * As[i * 64 + j];
            g_wef[((size_t)b * CD + o) * CD + h * 64 + j] = __float2half_rn(s);
        }
    }
}

// ======================= launch =======================
extern "C" void kernel_launch(void* const* d_in, const int* in_sizes, int n_in,
                              void* d_out, int out_size)
{
    const float* x     = (const float*)d_in[0];
    const float* Wq    = (const float*)d_in[1];
    const float* bq    = (const float*)d_in[2];
    const float* Wk    = (const float*)d_in[3];
    const float* bk    = (const float*)d_in[4];
    const float* Wv    = (const float*)d_in[5];
    const float* bv    = (const float*)d_in[6];
    const float* Woff1 = (const float*)d_in[7];
    const float* boff1 = (const float*)d_in[8];
    const float* Woff2 = (const float*)d_in[9];
    const float* boff2 = (const float*)d_in[10];
    const float* relb  = (const float*)d_in[11];
    const float* Wout  = (const float*)d_in[12];
    const float* bout  = (const float*)d_in[13];
    float* out = (float*)d_out;

    cudaFuncSetAttribute(gemm_f16,   cudaFuncAttributeMaxDynamicSharedMemorySize, FSMEM);
    cudaFuncSetAttribute(scores_f16, cudaFuncAttributeMaxDynamicSharedMemorySize, SSMEM);

    // order chosen so gemm_f16(q) is the 6th launch (ncu -s 5 -c 1 window)
    cvt_f16<<<(CB*CL*CD/4 + 255)/256, 256>>>(x,  CB*CL*CD/4, 0);   // 0
    cvt_f16<<<(CD*CD/4 + 255)/256,    256>>>(Wq, CD*CD/4,    1);   // 1
    cvt_f16<<<(CD*CD/4 + 255)/256,    256>>>(Wk, CD*CD/4,    2);   // 2
    cvt_f16<<<(CD*CD/4 + 255)/256,    256>>>(Wv, CD*CD/4,    3);   // 3
    compose_off<<<1, 640>>>(Woff1, boff1, Woff2, boff2);           // 4
    gemm_f16<<<dim3(64, 4, CB), 256, FSMEM>>>(bq, nullptr, 0);     // 5: q
    transpose_rb<<<dim3(CL/32, CD/32), dim3(32, 8)>>>(relb);       // 6
    offsets_fused<<<dim3(64, 16), 128>>>();                        // 7
    sampler_k<<<CB*CL/4, 512>>>(x);                                // 8
    gemm_f16<<<dim3(64, 4, CB), 256, FSMEM>>>(bk, nullptr, 1);     // 9: k
    gemm_f16<<<dim3(4, 64, CB), 256, FSMEM>>>(bv, nullptr, 2);     // 10: v
    scores_f16<<<dim3(32, 8), 256, SSMEM>>>();                     // 11
    softmax_k<<<32, 64>>>();                                       // 12
    weff_k<<<dim3(CB, 8), 256>>>(Wout);                            // 13
    gemm_f16<<<dim3(4, 64, CB), 256, FSMEM>>>(bout, out, 3);       // 14: final
}